// round 2
// baseline (speedup 1.0000x reference)
#include <cuda_runtime.h>
#include <cstdint>

// Problem constants (B=2, S=2048 -> T=4096 tokens)
#define NT_TOK 4096
#define DIM    2048
#define FDIM   4096
#define TWOF   8192
#define NEXP   8

// ---------------- static device scratch (sanctioned workaround) ----------------
__device__ int   g_cnt[9];
__device__ int   g_off[9];
__device__ int   g_list[NEXP * NT_TOK];
__device__ float g_gate[NEXP * NT_TOK];
// GEMM1 raw output (gate|up), rows: [0,T) routed slots, [T,2T) shared tokens
__device__ float g_C1[2 * NT_TOK * (size_t)TWOF];  // 256 MiB
// silu(gate)*up
__device__ float g_H [2 * NT_TOK * (size_t)FDIM];  // 128 MiB

// ---------------- helpers ----------------
__device__ __forceinline__ float to_tf32(float x) {
    uint32_t u;
    asm("cvt.rna.tf32.f32 %0, %1;" : "=r"(u) : "f"(x));
    return __uint_as_float(u);
}

__device__ __forceinline__ void mma_tf32(float c[4], const uint32_t a[4], const uint32_t b[2]) {
    asm volatile(
        "mma.sync.aligned.m16n8k8.row.col.f32.tf32.tf32.f32 "
        "{%0,%1,%2,%3}, {%4,%5,%6,%7}, {%8,%9}, {%0,%1,%2,%3};"
        : "+f"(c[0]), "+f"(c[1]), "+f"(c[2]), "+f"(c[3])
        : "r"(a[0]), "r"(a[1]), "r"(a[2]), "r"(a[3]), "r"(b[0]), "r"(b[1]));
}

// ---------------- router ----------------
__global__ void zero_kernel() {
    if (threadIdx.x < 9) g_cnt[threadIdx.x] = 0;
}

__global__ __launch_bounds__(256) void router_kernel(
    const float* __restrict__ x, const float* __restrict__ rw)
{
    int t = blockIdx.x;
    int tid = threadIdx.x;
    __shared__ float red[256];
    __shared__ float logits[8];

    float p[8];
#pragma unroll
    for (int e = 0; e < 8; e++) p[e] = 0.f;

    const float* xr = x + (size_t)t * DIM;
    for (int k = tid; k < DIM; k += 256) {
        float xv = xr[k];
#pragma unroll
        for (int e = 0; e < 8; e++) p[e] += xv * rw[e * DIM + k];
    }
    for (int e = 0; e < 8; e++) {
        red[tid] = p[e];
        __syncthreads();
        for (int s = 128; s > 0; s >>= 1) {
            if (tid < s) red[tid] += red[tid + s];
            __syncthreads();
        }
        if (tid == 0) logits[e] = red[0];
        __syncthreads();
    }
    if (tid == 0) {
        float best = logits[0]; int bi = 0;
#pragma unroll
        for (int e = 1; e < 8; e++) if (logits[e] > best) { best = logits[e]; bi = e; }
        float gate = 1.0f / (1.0f + expf(-best));
        int pos = atomicAdd(&g_cnt[bi], 1);
        g_list[bi * NT_TOK + pos] = t;
        g_gate[bi * NT_TOK + pos] = gate;
    }
}

__global__ void finalize_kernel() {
    int o = 0;
    for (int e = 0; e < 8; e++) { g_off[e] = o; o += g_cnt[e]; }
    g_off[8] = NT_TOK;
}

// ---------------- GEMM1: C1[slot, 0:2F] = (gate*x)[gathered] @ Wgu[g] ----------------
// grid: (TWOF/128, NT_TOK/128, 9), block 256
__global__ __launch_bounds__(256) void gemm1_kernel(
    const float* __restrict__ x,
    const float* __restrict__ wgu,
    const float* __restrict__ sgu)
{
    const int g   = blockIdx.z;
    const int cnt = (g < NEXP) ? g_cnt[g] : NT_TOK;
    const int m0  = blockIdx.y * 128;
    if (m0 >= cnt) return;
    const int n0  = blockIdx.x * 128;
    const float* Bw = (g < NEXP) ? (wgu + (size_t)g * DIM * TWOF) : sgu;
    const int rowbase = (g < NEXP) ? g_off[g] : NT_TOK;

    __shared__ float sA[128][36];
    __shared__ float sB[32][136];

    const int tid  = threadIdx.x;
    const int lane = tid & 31;
    const int wid  = tid >> 5;
    const int wm   = wid & 1;   // 2 row-warps x 64
    const int wn   = wid >> 1;  // 4 col-warps x 32

    const float* aptr[4];
    float scl[4];
#pragma unroll
    for (int i = 0; i < 4; i++) {
        int q = tid + 256 * i;
        int r = q >> 3;
        int row = m0 + r;
        if (g < NEXP) {
            if (row < cnt) {
                aptr[i] = x + (size_t)g_list[g * NT_TOK + row] * DIM;
                scl[i]  = g_gate[g * NT_TOK + row];
            } else { aptr[i] = x; scl[i] = 0.0f; }
        } else { aptr[i] = x + (size_t)row * DIM; scl[i] = 1.0f; }
    }

    float acc[4][4][4];
#pragma unroll
    for (int i = 0; i < 4; i++)
#pragma unroll
        for (int j = 0; j < 4; j++)
#pragma unroll
            for (int r = 0; r < 4; r++) acc[i][j][r] = 0.f;

    for (int kb = 0; kb < DIM; kb += 32) {
#pragma unroll
        for (int i = 0; i < 4; i++) {
            int q  = tid + 256 * i;
            int r  = q >> 3;
            int kc = (q & 7) * 4;
            float4 v = *(const float4*)(aptr[i] + kb + kc);
            float s = scl[i];
            sA[r][kc + 0] = to_tf32(v.x * s);
            sA[r][kc + 1] = to_tf32(v.y * s);
            sA[r][kc + 2] = to_tf32(v.z * s);
            sA[r][kc + 3] = to_tf32(v.w * s);
        }
#pragma unroll
        for (int i = 0; i < 4; i++) {
            int q  = tid + 256 * i;
            int kr = q >> 5;
            int cc = (q & 31) * 4;
            float4 v = *(const float4*)(Bw + (size_t)(kb + kr) * TWOF + n0 + cc);
            sB[kr][cc + 0] = to_tf32(v.x);
            sB[kr][cc + 1] = to_tf32(v.y);
            sB[kr][cc + 2] = to_tf32(v.z);
            sB[kr][cc + 3] = to_tf32(v.w);
        }
        __syncthreads();
#pragma unroll
        for (int ks = 0; ks < 4; ks++) {
            const int k = ks * 8;
            uint32_t af[4][4];
            uint32_t bf[4][2];
#pragma unroll
            for (int i = 0; i < 4; i++) {
                int mr = wm * 64 + i * 16 + (lane >> 2);
                int kc = k + (lane & 3);
                af[i][0] = __float_as_uint(sA[mr][kc]);
                af[i][1] = __float_as_uint(sA[mr + 8][kc]);
                af[i][2] = __float_as_uint(sA[mr][kc + 4]);
                af[i][3] = __float_as_uint(sA[mr + 8][kc + 4]);
            }
#pragma unroll
            for (int j = 0; j < 4; j++) {
                int nc = wn * 32 + j * 8 + (lane >> 2);
                int kr = k + (lane & 3);
                bf[j][0] = __float_as_uint(sB[kr][nc]);
                bf[j][1] = __float_as_uint(sB[kr + 4][nc]);
            }
#pragma unroll
            for (int i = 0; i < 4; i++)
#pragma unroll
                for (int j = 0; j < 4; j++)
                    mma_tf32(acc[i][j], af[i], bf[j]);
        }
        __syncthreads();
    }
    // epilogue: raw store to C1 scratch
#pragma unroll
    for (int i = 0; i < 4; i++) {
        int mrl = wm * 64 + i * 16 + (lane >> 2);
#pragma unroll
        for (int j = 0; j < 4; j++) {
            int nc = n0 + wn * 32 + j * 8 + (lane & 3) * 2;
            int row = m0 + mrl;
            if (row < cnt) {
                size_t o = (size_t)(rowbase + row) * TWOF + nc;
                g_C1[o]     = acc[i][j][0];
                g_C1[o + 1] = acc[i][j][1];
            }
            int row2 = row + 8;
            if (row2 < cnt) {
                size_t o = (size_t)(rowbase + row2) * TWOF + nc;
                g_C1[o]     = acc[i][j][2];
                g_C1[o + 1] = acc[i][j][3];
            }
        }
    }
}

// ---------------- silu(gate) * up ----------------
__global__ __launch_bounds__(256) void silu_kernel() {
    size_t idx = (size_t)blockIdx.x * 256 + threadIdx.x; // float4 index
    size_t e0  = idx * 4;
    size_t row = e0 >> 12;              // / FDIM
    int    j   = (int)(e0 & (FDIM - 1));
    float4 gv = *(const float4*)&g_C1[row * TWOF + j];
    float4 uv = *(const float4*)&g_C1[row * TWOF + FDIM + j];
    float4 h;
    h.x = gv.x / (1.f + expf(-gv.x)) * uv.x;
    h.y = gv.y / (1.f + expf(-gv.y)) * uv.y;
    h.z = gv.z / (1.f + expf(-gv.z)) * uv.z;
    h.w = gv.w / (1.f + expf(-gv.w)) * uv.w;
    *(float4*)&g_H[e0] = h;
}

// ---------------- GEMM2: out[tok, 0:D] (+)= H[slot] @ Wdn[g] ----------------
// grid: (DIM/128, NT_TOK/128, nz), block 256
__global__ __launch_bounds__(256) void gemm2_kernel(
    const float* __restrict__ wdn,
    const float* __restrict__ sdn,
    float* __restrict__ out,
    int gstart, int accumulate)
{
    const int g   = gstart + blockIdx.z;
    const int cnt = (g < NEXP) ? g_cnt[g] : NT_TOK;
    const int m0  = blockIdx.y * 128;
    if (m0 >= cnt) return;
    const int n0  = blockIdx.x * 128;
    const float* Bw = (g < NEXP) ? (wdn + (size_t)g * FDIM * DIM) : sdn;
    const int rowbase = (g < NEXP) ? g_off[g] : NT_TOK;

    __shared__ float sA[128][36];
    __shared__ float sB[32][136];

    const int tid  = threadIdx.x;
    const int lane = tid & 31;
    const int wid  = tid >> 5;
    const int wm   = wid & 1;
    const int wn   = wid >> 1;

    const float* aptr[4];
    bool aval[4];
#pragma unroll
    for (int i = 0; i < 4; i++) {
        int q = tid + 256 * i;
        int r = q >> 3;
        int row = m0 + r;
        aval[i] = (row < cnt);
        aptr[i] = g_H + (size_t)(rowbase + (aval[i] ? row : 0)) * FDIM;
    }

    float acc[4][4][4];
#pragma unroll
    for (int i = 0; i < 4; i++)
#pragma unroll
        for (int j = 0; j < 4; j++)
#pragma unroll
            for (int r = 0; r < 4; r++) acc[i][j][r] = 0.f;

    for (int kb = 0; kb < FDIM; kb += 32) {
#pragma unroll
        for (int i = 0; i < 4; i++) {
            int q  = tid + 256 * i;
            int r  = q >> 3;
            int kc = (q & 7) * 4;
            float4 v = make_float4(0.f, 0.f, 0.f, 0.f);
            if (aval[i]) v = *(const float4*)(aptr[i] + kb + kc);
            sA[r][kc + 0] = to_tf32(v.x);
            sA[r][kc + 1] = to_tf32(v.y);
            sA[r][kc + 2] = to_tf32(v.z);
            sA[r][kc + 3] = to_tf32(v.w);
        }
#pragma unroll
        for (int i = 0; i < 4; i++) {
            int q  = tid + 256 * i;
            int kr = q >> 5;
            int cc = (q & 31) * 4;
            float4 v = *(const float4*)(Bw + (size_t)(kb + kr) * DIM + n0 + cc);
            sB[kr][cc + 0] = to_tf32(v.x);
            sB[kr][cc + 1] = to_tf32(v.y);
            sB[kr][cc + 2] = to_tf32(v.z);
            sB[kr][cc + 3] = to_tf32(v.w);
        }
        __syncthreads();
#pragma unroll
        for (int ks = 0; ks < 4; ks++) {
            const int k = ks * 8;
            uint32_t af[4][4];
            uint32_t bf[4][2];
#pragma unroll
            for (int i = 0; i < 4; i++) {
                int mr = wm * 64 + i * 16 + (lane >> 2);
                int kc = k + (lane & 3);
                af[i][0] = __float_as_uint(sA[mr][kc]);
                af[i][1] = __float_as_uint(sA[mr + 8][kc]);
                af[i][2] = __float_as_uint(sA[mr][kc + 4]);
                af[i][3] = __float_as_uint(sA[mr + 8][kc + 4]);
            }
#pragma unroll
            for (int j = 0; j < 4; j++) {
                int nc = wn * 32 + j * 8 + (lane >> 2);
                int kr = k + (lane & 3);
                bf[j][0] = __float_as_uint(sB[kr][nc]);
                bf[j][1] = __float_as_uint(sB[kr + 4][nc]);
            }
#pragma unroll
            for (int i = 0; i < 4; i++)
#pragma unroll
                for (int j = 0; j < 4; j++)
                    mma_tf32(acc[i][j], af[i], bf[j]);
        }
        __syncthreads();
    }
    // epilogue: scatter to output rows; routed pass stores, shared pass adds
#pragma unroll
    for (int i = 0; i < 4; i++) {
        int mrl = wm * 64 + i * 16 + (lane >> 2);
#pragma unroll
        for (int j = 0; j < 4; j++) {
            int nc = n0 + wn * 32 + j * 8 + (lane & 3) * 2;
            int row = m0 + mrl;
            if (row < cnt) {
                int tok = (g < NEXP) ? g_list[g * NT_TOK + row] : row;
                size_t o = (size_t)tok * DIM + nc;
                if (accumulate) { out[o] += acc[i][j][0]; out[o + 1] += acc[i][j][1]; }
                else            { out[o]  = acc[i][j][0]; out[o + 1]  = acc[i][j][1]; }
            }
            int row2 = row + 8;
            if (row2 < cnt) {
                int tok = (g < NEXP) ? g_list[g * NT_TOK + row2] : row2;
                size_t o = (size_t)tok * DIM + nc;
                if (accumulate) { out[o] += acc[i][j][2]; out[o + 1] += acc[i][j][3]; }
                else            { out[o]  = acc[i][j][2]; out[o + 1]  = acc[i][j][3]; }
            }
        }
    }
}

// ---------------- launch ----------------
extern "C" void kernel_launch(void* const* d_in, const int* in_sizes, int n_in,
                              void* d_out, int out_size)
{
    const float* x   = (const float*)d_in[0];  // hidden_states (B,S,D)
    const float* rw  = (const float*)d_in[1];  // router_w (E,D)
    const float* wgu = (const float*)d_in[2];  // w_gate_up (E,D,2F)
    const float* wdn = (const float*)d_in[3];  // w_down (E,F,D)
    const float* sgu = (const float*)d_in[4];  // shared_gate_up (D,2F)
    const float* sdn = (const float*)d_in[5];  // shared_down (F,D)
    float* out = (float*)d_out;

    zero_kernel<<<1, 32>>>();
    router_kernel<<<NT_TOK, 256>>>(x, rw);
    finalize_kernel<<<1, 1>>>();
    gemm1_kernel<<<dim3(TWOF / 128, NT_TOK / 128, 9), 256>>>(x, wgu, sgu);
    silu_kernel<<<(2 * NT_TOK * (FDIM / 4)) / 256, 256>>>();
    // routed experts: exclusive plain stores (top-1 => each token row owned once)
    gemm2_kernel<<<dim3(DIM / 128, NT_TOK / 128, NEXP), 256>>>(wdn, sdn, out, 0, 0);
    // shared MLP: exclusive read-add-store on top (stream-ordered after routed pass)
    gemm2_kernel<<<dim3(DIM / 128, NT_TOK / 128, 1), 256>>>(wdn, sdn, out, 8, 1);
}

// round 7
// speedup vs baseline: 1.1767x; 1.1767x over previous
#include <cuda_runtime.h>
#include <cstdint>

// Problem constants (B=2, S=2048 -> T=4096 tokens)
#define NT_TOK 4096
#define DIM    2048
#define FDIM   4096
#define TWOF   8192
#define NEXP   8

// ---------------- static device scratch ----------------
__device__ int   g_cnt[9];
__device__ int   g_off[9];
__device__ int   g_list[NEXP * NT_TOK];
__device__ float g_gate[NEXP * NT_TOK];
// silu(gate)*up, rows: [0,T) routed slots, [T,2T) shared tokens (values pre-rounded to tf32)
__device__ float g_H[2 * NT_TOK * (size_t)FDIM];  // 128 MiB

// ---------------- helpers ----------------
__device__ __forceinline__ float to_tf32(float x) {
    uint32_t u;
    asm("cvt.rna.tf32.f32 %0, %1;" : "=r"(u) : "f"(x));
    return __uint_as_float(u);
}
__device__ __forceinline__ uint32_t tf32u(float x) {
    uint32_t u;
    asm("cvt.rna.tf32.f32 %0, %1;" : "=r"(u) : "f"(x));
    return u;
}
__device__ __forceinline__ void mma_tf32(float c[4], const uint32_t a[4], const uint32_t b[2]) {
    asm volatile(
        "mma.sync.aligned.m16n8k8.row.col.f32.tf32.tf32.f32 "
        "{%0,%1,%2,%3}, {%4,%5,%6,%7}, {%8,%9}, {%0,%1,%2,%3};"
        : "+f"(c[0]), "+f"(c[1]), "+f"(c[2]), "+f"(c[3])
        : "r"(a[0]), "r"(a[1]), "r"(a[2]), "r"(a[3]), "r"(b[0]), "r"(b[1]));
}
__device__ __forceinline__ void cp16(uint32_t dst, const void* src) {
    asm volatile("cp.async.cg.shared.global [%0], [%1], 16;\n" :: "r"(dst), "l"(src));
}
#define CP_COMMIT() asm volatile("cp.async.commit_group;\n")
#define CP_WAIT1()  asm volatile("cp.async.wait_group 1;\n")
#define CP_WAIT0()  asm volatile("cp.async.wait_group 0;\n")

// ---------------- router (warp per token) ----------------
__global__ void zero_kernel() {
    if (threadIdx.x < 9) g_cnt[threadIdx.x] = 0;
}

__global__ __launch_bounds__(256) void router_kernel(
    const float* __restrict__ x, const float* __restrict__ rw)
{
    int t    = blockIdx.x * 8 + (threadIdx.x >> 5);
    int lane = threadIdx.x & 31;
    const float* xr = x + (size_t)t * DIM;
    float p[8];
#pragma unroll
    for (int e = 0; e < 8; e++) p[e] = 0.f;
    for (int k = lane; k < DIM; k += 32) {
        float xv = xr[k];
#pragma unroll
        for (int e = 0; e < 8; e++) p[e] += xv * rw[e * DIM + k];
    }
#pragma unroll
    for (int e = 0; e < 8; e++) {
#pragma unroll
        for (int o = 16; o > 0; o >>= 1) p[e] += __shfl_xor_sync(~0u, p[e], o);
    }
    if (lane == 0) {
        float best = p[0]; int bi = 0;
#pragma unroll
        for (int e = 1; e < 8; e++) if (p[e] > best) { best = p[e]; bi = e; }
        float gate = 1.0f / (1.0f + expf(-best));
        int pos = atomicAdd(&g_cnt[bi], 1);
        g_list[bi * NT_TOK + pos] = t;
        g_gate[bi * NT_TOK + pos] = gate;
    }
}

__global__ void finalize_kernel() {
    int o = 0;
    for (int e = 0; e < 8; e++) { g_off[e] = o; o += g_cnt[e]; }
    g_off[8] = NT_TOK;
}

// ---------------- GEMM1 fused: H[slot] = silu(gx@Wg) * (gx@Wu) ----------------
// Block computes 128 rows x 64 gate-cols AND the matching 64 up-cols.
// grid: (FDIM/64, NT_TOK/128, 9), block 256.
// smem layout (dynamic): sA[2][128][36] | sBg[2][32][72] | sBu[2][32][72]
#define G1_SA_ST  36
#define G1_SB_ST  72
#define G1_SA_SZ  (128 * G1_SA_ST)
#define G1_SB_SZ  (32 * G1_SB_ST)
#define G1_SMEM_BYTES ((2 * G1_SA_SZ + 4 * G1_SB_SZ) * 4)

__global__ __launch_bounds__(256) void gemm1_kernel(
    const float* __restrict__ x,
    const float* __restrict__ wgu,
    const float* __restrict__ sgu)
{
    const int g   = blockIdx.z;
    const int cnt = (g < NEXP) ? g_cnt[g] : NT_TOK;
    const int m0  = blockIdx.y * 128;
    if (m0 >= cnt) return;
    const int n0  = blockIdx.x * 64;
    const float* Bw = (g < NEXP) ? (wgu + (size_t)g * DIM * TWOF) : sgu;
    const int rowbase = (g < NEXP) ? g_off[g] : NT_TOK;

    extern __shared__ float sm[];
    float* sA  = sm;
    float* sBg = sm + 2 * G1_SA_SZ;
    float* sBu = sBg + 2 * G1_SB_SZ;

    const int tid  = threadIdx.x;
    const int lane = tid & 31;
    const int wid  = tid >> 5;
    const int wm   = wid & 3;   // 4 row-warps x 32
    const int wn   = wid >> 2;  // 2 col-warps x 32 (per half)

    // A source rows for this thread's 4 cp.async chunks
    const float* aptr[4];
#pragma unroll
    for (int i = 0; i < 4; i++) {
        int r = (tid >> 3) + 32 * i;
        int row = m0 + r;
        if (g < NEXP) {
            int rr = (row < cnt) ? row : 0;
            aptr[i] = x + (size_t)g_list[g * NT_TOK + rr] * DIM;
        } else {
            aptr[i] = x + (size_t)row * DIM;
        }
    }
    const int ac4 = (tid & 7) * 4;

    // gate per fragment row (0 for out-of-range routed rows -> zero A)
    float gfr[2][2];
#pragma unroll
    for (int i = 0; i < 2; i++) {
        int mr = wm * 32 + i * 16 + (lane >> 2);
#pragma unroll
        for (int h = 0; h < 2; h++) {
            int row = m0 + mr + h * 8;
            float gv;
            if (g < NEXP) gv = (row < cnt) ? g_gate[g * NT_TOK + row] : 0.f;
            else          gv = 1.f;
            gfr[i][h] = gv;
        }
    }

    float acc[2][2][4][4];  // [half][mi][nj][r]
#pragma unroll
    for (int h = 0; h < 2; h++)
#pragma unroll
        for (int i = 0; i < 2; i++)
#pragma unroll
            for (int j = 0; j < 4; j++)
#pragma unroll
                for (int r = 0; r < 4; r++) acc[h][i][j][r] = 0.f;

    const int ar = tid >> 3;
    const int bkr = (tid >> 4) & 15;      // q=tid: kr for i=0 chunk
    const int bcc = (tid & 15) * 4;

#define G1_LOAD(bufv, kbv) do {                                                   \
        uint32_t sab = (uint32_t)__cvta_generic_to_shared(sA + (bufv) * G1_SA_SZ);\
        _Pragma("unroll")                                                         \
        for (int i = 0; i < 4; i++)                                               \
            cp16(sab + ((ar + 32 * i) * G1_SA_ST + ac4) * 4, aptr[i] + (kbv) + ac4);\
        uint32_t sgb = (uint32_t)__cvta_generic_to_shared(sBg + (bufv) * G1_SB_SZ);\
        uint32_t sub = (uint32_t)__cvta_generic_to_shared(sBu + (bufv) * G1_SB_SZ);\
        _Pragma("unroll")                                                         \
        for (int i = 0; i < 2; i++) {                                             \
            int kr = bkr + 16 * i;                                                \
            const float* srow = Bw + (size_t)((kbv) + kr) * TWOF + n0;            \
            cp16(sgb + (kr * G1_SB_ST + bcc) * 4, srow + bcc);                    \
            cp16(sub + (kr * G1_SB_ST + bcc) * 4, srow + FDIM + bcc);             \
        }                                                                         \
    } while (0)

    G1_LOAD(0, 0); CP_COMMIT();
    const int ITERS = DIM / 32;
    int buf = 0;
    for (int it = 0; it < ITERS; it++) {
        if (it + 1 < ITERS) { G1_LOAD(buf ^ 1, (it + 1) * 32); CP_COMMIT(); CP_WAIT1(); }
        else                { CP_WAIT0(); }
        __syncthreads();
        const float* A  = sA  + buf * G1_SA_SZ;
        const float* Bg = sBg + buf * G1_SB_SZ;
        const float* Bu = sBu + buf * G1_SB_SZ;
#pragma unroll
        for (int ks = 0; ks < 4; ks++) {
            const int k = ks * 8;
            uint32_t af[2][4];
#pragma unroll
            for (int i = 0; i < 2; i++) {
                int mr = wm * 32 + i * 16 + (lane >> 2);
                int kc = k + (lane & 3);
                af[i][0] = tf32u(A[mr * G1_SA_ST + kc]       * gfr[i][0]);
                af[i][1] = tf32u(A[(mr + 8) * G1_SA_ST + kc] * gfr[i][1]);
                af[i][2] = tf32u(A[mr * G1_SA_ST + kc + 4]       * gfr[i][0]);
                af[i][3] = tf32u(A[(mr + 8) * G1_SA_ST + kc + 4] * gfr[i][1]);
            }
            uint32_t bf[2][4][2];
#pragma unroll
            for (int j = 0; j < 4; j++) {
                int nc = wn * 32 + j * 8 + (lane >> 2);
                int kr = k + (lane & 3);
                bf[0][j][0] = tf32u(Bg[kr * G1_SB_ST + nc]);
                bf[0][j][1] = tf32u(Bg[(kr + 4) * G1_SB_ST + nc]);
                bf[1][j][0] = tf32u(Bu[kr * G1_SB_ST + nc]);
                bf[1][j][1] = tf32u(Bu[(kr + 4) * G1_SB_ST + nc]);
            }
#pragma unroll
            for (int h = 0; h < 2; h++)
#pragma unroll
                for (int i = 0; i < 2; i++)
#pragma unroll
                    for (int j = 0; j < 4; j++)
                        mma_tf32(acc[h][i][j], af[i], bf[h][j]);
        }
        __syncthreads();
        buf ^= 1;
    }

    // epilogue: h = silu(gate)*up, pre-rounded to tf32 for gemm2's A path
#pragma unroll
    for (int i = 0; i < 2; i++) {
        int mr = wm * 32 + i * 16 + (lane >> 2);
#pragma unroll
        for (int j = 0; j < 4; j++) {
            int nc = n0 + wn * 32 + j * 8 + (lane & 3) * 2;
            int row = m0 + mr;
            if (row < cnt) {
                float gv0 = acc[0][i][j][0], uv0 = acc[1][i][j][0];
                float gv1 = acc[0][i][j][1], uv1 = acc[1][i][j][1];
                float2 hv;
                hv.x = to_tf32(gv0 / (1.f + expf(-gv0)) * uv0);
                hv.y = to_tf32(gv1 / (1.f + expf(-gv1)) * uv1);
                *(float2*)&g_H[(size_t)(rowbase + row) * FDIM + nc] = hv;
            }
            int row2 = row + 8;
            if (row2 < cnt) {
                float gv0 = acc[0][i][j][2], uv0 = acc[1][i][j][2];
                float gv1 = acc[0][i][j][3], uv1 = acc[1][i][j][3];
                float2 hv;
                hv.x = to_tf32(gv0 / (1.f + expf(-gv0)) * uv0);
                hv.y = to_tf32(gv1 / (1.f + expf(-gv1)) * uv1);
                *(float2*)&g_H[(size_t)(rowbase + row2) * FDIM + nc] = hv;
            }
        }
    }
}

// ---------------- GEMM2: out[tok] (+)= H[slot] @ Wdn[g] ----------------
// grid: (DIM/128, NT_TOK/128, nz), block 256.
// smem: sA[2][128][36] | sB[2][32][136]
#define G2_SA_ST  36
#define G2_SB_ST  136
#define G2_SA_SZ  (128 * G2_SA_ST)
#define G2_SB_SZ  (32 * G2_SB_ST)
#define G2_SMEM_BYTES ((2 * G2_SA_SZ + 2 * G2_SB_SZ) * 4)

__global__ __launch_bounds__(256) void gemm2_kernel(
    const float* __restrict__ wdn,
    const float* __restrict__ sdn,
    float* __restrict__ out,
    int gstart, int accumulate)
{
    const int g   = gstart + blockIdx.z;
    const int cnt = (g < NEXP) ? g_cnt[g] : NT_TOK;
    const int m0  = blockIdx.y * 128;
    if (m0 >= cnt) return;
    const int n0  = blockIdx.x * 128;
    const float* Bw = (g < NEXP) ? (wdn + (size_t)g * FDIM * DIM) : sdn;
    const int rowbase = (g < NEXP) ? g_off[g] : NT_TOK;

    extern __shared__ float sm[];
    float* sA = sm;
    float* sB = sm + 2 * G2_SA_SZ;

    const int tid  = threadIdx.x;
    const int lane = tid & 31;
    const int wid  = tid >> 5;
    const int wm   = wid & 1;   // 2 row-warps x 64
    const int wn   = wid >> 1;  // 4 col-warps x 32

    const float* aptr[4];
#pragma unroll
    for (int i = 0; i < 4; i++) {
        int r = (tid >> 3) + 32 * i;
        int row = m0 + r;
        int rr = (row < cnt) ? row : 0;
        aptr[i] = g_H + (size_t)(rowbase + rr) * FDIM;
    }
    const int ac4 = (tid & 7) * 4;
    const int ar  = tid >> 3;
    const int bkr0 = tid >> 5;            // q=tid: kr
    const int bcc  = (tid & 31) * 4;

    float acc[4][4][4];
#pragma unroll
    for (int i = 0; i < 4; i++)
#pragma unroll
        for (int j = 0; j < 4; j++)
#pragma unroll
            for (int r = 0; r < 4; r++) acc[i][j][r] = 0.f;

#define G2_LOAD(bufv, kbv) do {                                                   \
        uint32_t sab = (uint32_t)__cvta_generic_to_shared(sA + (bufv) * G2_SA_SZ);\
        _Pragma("unroll")                                                         \
        for (int i = 0; i < 4; i++)                                               \
            cp16(sab + ((ar + 32 * i) * G2_SA_ST + ac4) * 4, aptr[i] + (kbv) + ac4);\
        uint32_t sbb = (uint32_t)__cvta_generic_to_shared(sB + (bufv) * G2_SB_SZ);\
        _Pragma("unroll")                                                         \
        for (int i = 0; i < 4; i++) {                                             \
            int kr = bkr0 + 8 * i;                                                \
            cp16(sbb + (kr * G2_SB_ST + bcc) * 4,                                 \
                 Bw + (size_t)((kbv) + kr) * DIM + n0 + bcc);                     \
        }                                                                         \
    } while (0)

    G2_LOAD(0, 0); CP_COMMIT();
    const int ITERS = FDIM / 32;
    int buf = 0;
    for (int it = 0; it < ITERS; it++) {
        if (it + 1 < ITERS) { G2_LOAD(buf ^ 1, (it + 1) * 32); CP_COMMIT(); CP_WAIT1(); }
        else                { CP_WAIT0(); }
        __syncthreads();
        const float* A = sA + buf * G2_SA_SZ;
        const float* B = sB + buf * G2_SB_SZ;
#pragma unroll
        for (int ks = 0; ks < 4; ks++) {
            const int k = ks * 8;
            uint32_t af[4][4];
#pragma unroll
            for (int i = 0; i < 4; i++) {
                int mr = wm * 64 + i * 16 + (lane >> 2);
                int kc = k + (lane & 3);
                // g_H values are pre-rounded tf32: no cvt needed
                af[i][0] = __float_as_uint(A[mr * G2_SA_ST + kc]);
                af[i][1] = __float_as_uint(A[(mr + 8) * G2_SA_ST + kc]);
                af[i][2] = __float_as_uint(A[mr * G2_SA_ST + kc + 4]);
                af[i][3] = __float_as_uint(A[(mr + 8) * G2_SA_ST + kc + 4]);
            }
            uint32_t bf[4][2];
#pragma unroll
            for (int j = 0; j < 4; j++) {
                int nc = wn * 32 + j * 8 + (lane >> 2);
                int kr = k + (lane & 3);
                bf[j][0] = tf32u(B[kr * G2_SB_ST + nc]);
                bf[j][1] = tf32u(B[(kr + 4) * G2_SB_ST + nc]);
            }
#pragma unroll
            for (int i = 0; i < 4; i++)
#pragma unroll
                for (int j = 0; j < 4; j++)
                    mma_tf32(acc[i][j], af[i], bf[j]);
        }
        __syncthreads();
        buf ^= 1;
    }

    // epilogue: routed pass plain stores (top-1 => exclusive rows), shared pass adds
#pragma unroll
    for (int i = 0; i < 4; i++) {
        int mrl = wm * 64 + i * 16 + (lane >> 2);
#pragma unroll
        for (int j = 0; j < 4; j++) {
            int nc = n0 + wn * 32 + j * 8 + (lane & 3) * 2;
            int row = m0 + mrl;
            if (row < cnt) {
                int tok = (g < NEXP) ? g_list[g * NT_TOK + row] : row;
                size_t o = (size_t)tok * DIM + nc;
                if (accumulate) { out[o] += acc[i][j][0]; out[o + 1] += acc[i][j][1]; }
                else            { out[o]  = acc[i][j][0]; out[o + 1]  = acc[i][j][1]; }
            }
            int row2 = row + 8;
            if (row2 < cnt) {
                int tok = (g < NEXP) ? g_list[g * NT_TOK + row2] : row2;
                size_t o = (size_t)tok * DIM + nc;
                if (accumulate) { out[o] += acc[i][j][2]; out[o + 1] += acc[i][j][3]; }
                else            { out[o]  = acc[i][j][2]; out[o + 1]  = acc[i][j][3]; }
            }
        }
    }
}

// ---------------- launch ----------------
extern "C" void kernel_launch(void* const* d_in, const int* in_sizes, int n_in,
                              void* d_out, int out_size)
{
    const float* x   = (const float*)d_in[0];
    const float* rw  = (const float*)d_in[1];
    const float* wgu = (const float*)d_in[2];
    const float* wdn = (const float*)d_in[3];
    const float* sgu = (const float*)d_in[4];
    const float* sdn = (const float*)d_in[5];
    float* out = (float*)d_out;

    cudaFuncSetAttribute(gemm1_kernel, cudaFuncAttributeMaxDynamicSharedMemorySize, G1_SMEM_BYTES);
    cudaFuncSetAttribute(gemm2_kernel, cudaFuncAttributeMaxDynamicSharedMemorySize, G2_SMEM_BYTES);

    zero_kernel<<<1, 32>>>();
    router_kernel<<<NT_TOK / 8, 256>>>(x, rw);
    finalize_kernel<<<1, 1>>>();
    gemm1_kernel<<<dim3(FDIM / 64, NT_TOK / 128, 9), 256, G1_SMEM_BYTES>>>(x, wgu, sgu);
    gemm2_kernel<<<dim3(DIM / 128, NT_TOK / 128, NEXP), 256, G2_SMEM_BYTES>>>(wdn, sdn, out, 0, 0);
    gemm2_kernel<<<dim3(DIM / 128, NT_TOK / 128, 1), 256, G2_SMEM_BYTES>>>(wdn, sdn, out, 8, 1);
}

// round 9
// speedup vs baseline: 2.5819x; 2.1941x over previous
#include <cuda_runtime.h>
#include <cstdint>

#define NT_TOK 4096
#define DIM    2048
#define FDIM   4096
#define TWOF   8192
#define NEXP   8

// ---------------- static device scratch ----------------
__device__ int   g_cnt[9];
__device__ int   g_off[9];
__device__ int   g_list[NEXP * NT_TOK];
__device__ float g_gate[NEXP * NT_TOK];
// silu(gate)*up, rows: [0,T) routed slots, [T,2T) shared tokens (tf32-rounded)
__device__ float g_H[2 * NT_TOK * (size_t)FDIM];  // 128 MiB

// ---------------- helpers (arch-neutral) ----------------
__device__ __forceinline__ float to_tf32(float x) {
    uint32_t u; asm("cvt.rna.tf32.f32 %0, %1;" : "=r"(u) : "f"(x));
    return __uint_as_float(u);
}
__device__ __forceinline__ uint32_t tf32u(float x) {
    uint32_t u; asm("cvt.rna.tf32.f32 %0, %1;" : "=r"(u) : "f"(x));
    return u;
}
__device__ __forceinline__ uint32_t smem_u32(const void* p) {
    uint32_t a;
    asm("{ .reg .u64 t; cvta.to.shared.u64 t, %1; cvt.u32.u64 %0, t; }" : "=r"(a) : "l"(p));
    return a;
}
#define SW128(o) ((o) ^ (((o) >> 3) & 0x70))

// Only the sm_103a (arch-specific) pass gets tcgen05; the portable compute_103
// pass compiles a correct naive fallback body instead (tcgen05 is 'a'-only).
#if defined(__CUDA_ARCH__) && defined(__CUDA_ARCH_FEAT_SM103_ALL)
#define HAS_TCGEN05 1
#else
#define HAS_TCGEN05 0
#endif

#if HAS_TCGEN05
__device__ __forceinline__ uint32_t elect_one() {
    uint32_t p;
    asm volatile("{\n\t.reg .pred p;\n\telect.sync _|p, 0xFFFFFFFF;\n\t"
                 "selp.b32 %0, 1, 0, p;\n\t}" : "=r"(p));
    return p;
}
static __device__ __forceinline__ uint64_t make_desc_sw128(uint32_t addr) {
    const uint64_t base =
        (uint64_t(2) << 61) | (uint64_t(1) << 46) | (uint64_t(64) << 32) | (uint64_t(1) << 16);
    return base | ((uint64_t)(addr >> 4) & 0x3FFF);
}
// idesc: dtype=F32(1)<<4 | atype=TF32(2)<<7 | btype=TF32(2)<<10 | (N/8)<<17 | (M/16)<<24
#define IDESC_TF32_M128_N256 ((1u<<4)|(2u<<7)|(2u<<10)|((256u/8)<<17)|((128u/16)<<24))

__device__ __forceinline__ void mma_tf32_ss(uint32_t d, uint64_t da, uint64_t db,
                                            uint32_t idesc, uint32_t en) {
    asm volatile(
        "{\n\t.reg .pred p;\n\tsetp.ne.u32 p, %4, 0;\n\t"
        "tcgen05.mma.cta_group::1.kind::tf32 [%0], %1, %2, %3, {%5, %5, %5, %5}, p;\n\t}"
        :: "r"(d), "l"(da), "l"(db), "r"(idesc), "r"(en), "r"(0u) : "memory");
}

#define TC_ALLOC(sm, n)   asm volatile("tcgen05.alloc.cta_group::1.sync.aligned.shared::cta.b32 [%0], %1;" :: "r"(sm), "r"(n) : "memory")
#define TC_DEALLOC(tb, n) asm volatile("tcgen05.dealloc.cta_group::1.sync.aligned.b32 %0, %1;" :: "r"(tb), "r"(n))
#define TC_RELINQ()       asm volatile("tcgen05.relinquish_alloc_permit.cta_group::1.sync.aligned;")
#define TC_COMMIT(mb)     asm volatile("tcgen05.commit.cta_group::1.mbarrier::arrive::one.shared::cluster.b64 [%0];" :: "r"(mb) : "memory")
#define TC_FENCE_AFTER()  asm volatile("tcgen05.fence::after_thread_sync;" ::: "memory")
#define TC_WAIT_LD()      asm volatile("tcgen05.wait::ld.sync.aligned;" ::: "memory")
#define FENCE_ASYNC()     asm volatile("fence.proxy.async.shared::cta;" ::: "memory")
#define MBAR_INIT(mb, c)  asm volatile("mbarrier.init.shared.b64 [%0], %1;" :: "r"(mb), "r"(c) : "memory")
#define MBAR_INVAL(mb)    asm volatile("mbarrier.inval.shared.b64 [%0];" :: "r"(mb) : "memory")

#define MBAR_WAIT(mb, ph) do {                                                       \
    uint32_t _m = (mb); uint32_t _p = (ph); uint32_t _d;                             \
    asm volatile("{\n\t.reg .pred p;\n\t"                                            \
        "mbarrier.try_wait.parity.acquire.cta.shared::cta.b64 p, [%1], %2;\n\t"      \
        "selp.b32 %0, 1, 0, p;\n\t}" : "=r"(_d) : "r"(_m), "r"(_p) : "memory");      \
    if (!_d) {                                                                       \
        asm volatile("{\n\t.reg .pred P1;\n\tWL_%=:\n\t"                             \
            "mbarrier.try_wait.parity.acquire.cta.shared::cta.b64 P1, [%0], %1, 0x989680;\n\t" \
            "@P1 bra.uni WD_%=;\n\tbra.uni WL_%=;\n\tWD_%=:\n\t}"                    \
            :: "r"(_m), "r"(_p) : "memory");                                         \
    }                                                                                \
} while (0)

#define TC_LD_X32(r, addr)                                                           \
    asm volatile("tcgen05.ld.sync.aligned.32x32b.x32.b32 "                           \
        "{%0,%1,%2,%3,%4,%5,%6,%7,%8,%9,%10,%11,%12,%13,%14,%15,"                    \
        "%16,%17,%18,%19,%20,%21,%22,%23,%24,%25,%26,%27,%28,%29,%30,%31}, [%32];"   \
        : "=r"((r)[0]),"=r"((r)[1]),"=r"((r)[2]),"=r"((r)[3]),                       \
          "=r"((r)[4]),"=r"((r)[5]),"=r"((r)[6]),"=r"((r)[7]),                       \
          "=r"((r)[8]),"=r"((r)[9]),"=r"((r)[10]),"=r"((r)[11]),                     \
          "=r"((r)[12]),"=r"((r)[13]),"=r"((r)[14]),"=r"((r)[15]),                   \
          "=r"((r)[16]),"=r"((r)[17]),"=r"((r)[18]),"=r"((r)[19]),                   \
          "=r"((r)[20]),"=r"((r)[21]),"=r"((r)[22]),"=r"((r)[23]),                   \
          "=r"((r)[24]),"=r"((r)[25]),"=r"((r)[26]),"=r"((r)[27]),                   \
          "=r"((r)[28]),"=r"((r)[29]),"=r"((r)[30]),"=r"((r)[31])                    \
        : "r"(addr))

#define STS128(addr, a, b, c, d)                                                     \
    asm volatile("st.shared.v4.b32 [%0], {%1, %2, %3, %4};"                          \
                 :: "r"(addr), "r"(a), "r"(b), "r"(c), "r"(d) : "memory")
#endif  // HAS_TCGEN05

// smem layout: [align to 1024] hdr(1024): mb0@0 mb1@8 tmemptr@16 ; buffers @1024
#define STAGE_BYTES 65536          // A 32KB + B 32KB
#define SMEM_BYTES  (1024 + 1024 + 2 * STAGE_BYTES)

// ---------------- router ----------------
__global__ void zero_kernel() { if (threadIdx.x < 9) g_cnt[threadIdx.x] = 0; }

__global__ __launch_bounds__(256) void router_kernel(
    const float* __restrict__ x, const float* __restrict__ rw)
{
    int t = blockIdx.x * 8 + (threadIdx.x >> 5);
    int lane = threadIdx.x & 31;
    const float* xr = x + (size_t)t * DIM;
    float p[8];
#pragma unroll
    for (int e = 0; e < 8; e++) p[e] = 0.f;
    for (int k = lane; k < DIM; k += 32) {
        float xv = xr[k];
#pragma unroll
        for (int e = 0; e < 8; e++) p[e] += xv * rw[e * DIM + k];
    }
#pragma unroll
    for (int e = 0; e < 8; e++)
#pragma unroll
        for (int o = 16; o > 0; o >>= 1) p[e] += __shfl_xor_sync(~0u, p[e], o);
    if (lane == 0) {
        float best = p[0]; int bi = 0;
#pragma unroll
        for (int e = 1; e < 8; e++) if (p[e] > best) { best = p[e]; bi = e; }
        float gate = 1.0f / (1.0f + expf(-best));
        int pos = atomicAdd(&g_cnt[bi], 1);
        g_list[bi * NT_TOK + pos] = t;
        g_gate[bi * NT_TOK + pos] = gate;
    }
}

__global__ void finalize_kernel() {
    int o = 0;
    for (int e = 0; e < 8; e++) { g_off[e] = o; o += g_cnt[e]; }
    g_off[8] = NT_TOK;
}

// ================= GEMM1: H = silu(gx@Wg) * (gx@Wu) =================
// Block tile: M=256 tokens x 128 h-cols (gate 128 + up 128 = N 256).
// grid: (FDIM/128, NT_TOK/256, 9), block 512.
__global__ __launch_bounds__(512, 1) void gemm1_tc(
    const float* __restrict__ x,
    const float* __restrict__ wgu,
    const float* __restrict__ sgu)
{
    const int g   = blockIdx.z;
    const int cnt = (g < NEXP) ? g_cnt[g] : NT_TOK;
    const int m0  = blockIdx.y * 256;
    if (m0 >= cnt) return;
    const int hb  = blockIdx.x;
    const float* Bsrc = (g < NEXP) ? (wgu + (size_t)g * DIM * TWOF) : sgu;
    const int rowbase = (g < NEXP) ? g_off[g] : NT_TOK;

#if HAS_TCGEN05
    extern __shared__ char smraw[];
    uint32_t sb  = (smem_u32(smraw) + 1023u) & ~1023u;
    const uint32_t MB0 = sb, MB1 = sb + 8, TP = sb + 16;
    const uint32_t BUF = sb + 1024;

    const int tid = threadIdx.x, wid = tid >> 5, lane = tid & 31;

    if (wid == 0) { TC_ALLOC(TP, 512); TC_RELINQ(); }
    if (tid == 0) { MBAR_INIT(MB0, 1); MBAR_INIT(MB1, 1); }
    __syncthreads();
    uint32_t tb;
    asm volatile("ld.shared.b32 %0, [%1];" : "=r"(tb) : "r"(TP));

    // ---- A mapping: thread covers 4 chunks of float4; rows arow + 64*j ----
    const int arow = tid >> 3;
    const int akc  = (tid & 7) * 4;
    const float* aptr[4]; float agate[4];
#pragma unroll
    for (int j = 0; j < 4; j++) {
        int row = m0 + arow + 64 * j;
        if (g < NEXP) {
            if (row < cnt) { aptr[j] = x + (size_t)g_list[g * NT_TOK + row] * DIM; agate[j] = g_gate[g * NT_TOK + row]; }
            else           { aptr[j] = x + (size_t)g_list[g * NT_TOK] * DIM;      agate[j] = 0.f; }
        } else { aptr[j] = x + (size_t)row * DIM; agate[j] = 1.f; }
    }
    // ---- B mapping: warp w covers smem rows n in [16w,16w+16) ----
    const int bn   = wid * 16 + (lane & 15);
    const int bk0  = (lane >> 4) * 4;
    const int gcol = (bn < 128) ? (hb * 128 + bn) : (FDIM + hb * 128 + bn - 128);
    const float* bptr = Bsrc + gcol;

    float4 rA[4]; float rB[4][4];
#pragma unroll
    for (int j = 0; j < 4; j++) rA[j] = *(const float4*)(aptr[j] + akc);
#pragma unroll
    for (int i = 0; i < 4; i++)
#pragma unroll
        for (int d = 0; d < 4; d++) rB[i][d] = bptr[(size_t)(bk0 + 8 * i + d) * TWOF];

    int ph0 = 0, ph1 = 0;
    const int T = DIM / 32;
    for (int t = 0; t < T; t++) {
        const int buf = t & 1;
        const uint32_t Ab = BUF + buf * STAGE_BYTES;
        const uint32_t Bb = Ab + 32768;
        if (t >= 2) { if (buf == 0) { MBAR_WAIT(MB0, ph0); ph0 ^= 1; } else { MBAR_WAIT(MB1, ph1); ph1 ^= 1; } }
#pragma unroll
        for (int j = 0; j < 4; j++) {
            float s = agate[j];
            uint32_t v0 = tf32u(rA[j].x * s), v1 = tf32u(rA[j].y * s);
            uint32_t v2 = tf32u(rA[j].z * s), v3 = tf32u(rA[j].w * s);
            uint32_t off = (uint32_t)((arow + 64 * j) * 128 + akc * 4);
            STS128(Ab + SW128(off), v0, v1, v2, v3);
        }
#pragma unroll
        for (int i = 0; i < 4; i++) {
            uint32_t v0 = tf32u(rB[i][0]), v1 = tf32u(rB[i][1]);
            uint32_t v2 = tf32u(rB[i][2]), v3 = tf32u(rB[i][3]);
            uint32_t off = (uint32_t)(bn * 128 + (bk0 + 8 * i) * 4);
            STS128(Bb + SW128(off), v0, v1, v2, v3);
        }
        FENCE_ASYNC();
        __syncthreads();
        if (wid == 0 && elect_one()) {
            uint64_t dA0 = make_desc_sw128(Ab);
            uint64_t dA1 = make_desc_sw128(Ab + 16384);
            uint64_t dB  = make_desc_sw128(Bb);
#pragma unroll
            for (int c = 0; c < 4; c++) {
                uint32_t en = (t > 0 || c > 0) ? 1u : 0u;
                mma_tf32_ss(tb,       dA0 + c * 2, dB + c * 2, IDESC_TF32_M128_N256, en);
                mma_tf32_ss(tb + 256, dA1 + c * 2, dB + c * 2, IDESC_TF32_M128_N256, en);
            }
            TC_COMMIT(buf ? MB1 : MB0);
        }
        if (t + 1 < T) {
            int kb = (t + 1) * 32;
#pragma unroll
            for (int j = 0; j < 4; j++) rA[j] = *(const float4*)(aptr[j] + kb + akc);
#pragma unroll
            for (int i = 0; i < 4; i++)
#pragma unroll
                for (int d = 0; d < 4; d++) rB[i][d] = bptr[(size_t)(kb + bk0 + 8 * i + d) * TWOF];
        }
    }
    { const int lb = (T - 1) & 1;
      if (lb == 0) { MBAR_WAIT(MB0, ph0); } else { MBAR_WAIT(MB1, ph1); } }
    TC_FENCE_AFTER();

    // ---- epilogue: silu(g)*u -> g_H ----
    const int mh = (wid >> 2) & 1, half = wid >> 3, subp = wid & 3;
    const int row = m0 + mh * 128 + subp * 32 + lane;
    const bool ok = row < cnt;
    const size_t hbase = (size_t)(rowbase + row) * FDIM + hb * 128 + half * 64;
#pragma unroll
    for (int c = 0; c < 2; c++) {
        uint32_t gr[32], ur[32];
        uint32_t col = (uint32_t)(mh * 256 + half * 64 + c * 32);
        TC_LD_X32(gr, tb + col);
        TC_LD_X32(ur, tb + col + 128);
        TC_WAIT_LD();
        if (ok) {
            float h[32];
#pragma unroll
            for (int r = 0; r < 32; r++) {
                float gv = __uint_as_float(gr[r]), uv = __uint_as_float(ur[r]);
                h[r] = to_tf32(gv / (1.f + expf(-gv)) * uv);
            }
#pragma unroll
            for (int q = 0; q < 8; q++)
                *(float4*)&g_H[hbase + c * 32 + q * 4] = make_float4(h[q*4], h[q*4+1], h[q*4+2], h[q*4+3]);
        }
    }
    __syncthreads();
    if (tid == 0) { MBAR_INVAL(MB0); MBAR_INVAL(MB1); }
    if (wid == 0) { TC_DEALLOC(tb, 512); }
#else
    // ---- portable fallback (compute_103 PTX pass; correct but naive) ----
    for (int idx = threadIdx.x; idx < 256 * 128; idx += 512) {
        int r  = idx >> 7;
        int cc = idx & 127;
        int row = m0 + r;
        if (row >= cnt) continue;
        const float* arow; float gate;
        if (g < NEXP) { arow = x + (size_t)g_list[g * NT_TOK + row] * DIM; gate = g_gate[g * NT_TOK + row]; }
        else          { arow = x + (size_t)row * DIM; gate = 1.f; }
        int col = hb * 128 + cc;
        float sg = 0.f, su = 0.f;
        for (int k = 0; k < DIM; k++) {
            float a = to_tf32(arow[k] * gate);
            sg += a * to_tf32(Bsrc[(size_t)k * TWOF + col]);
            su += a * to_tf32(Bsrc[(size_t)k * TWOF + FDIM + col]);
        }
        g_H[(size_t)(rowbase + row) * FDIM + col] = to_tf32(sg / (1.f + expf(-sg)) * su);
    }
#endif
}

// ================= GEMM2: out (+)= H @ Wdn =================
// Block tile: M=256 slots x N=256 out-cols. grid: (DIM/256, NT_TOK/256, nz), block 512.
__global__ __launch_bounds__(512, 1) void gemm2_tc(
    const float* __restrict__ wdn,
    const float* __restrict__ sdn,
    float* __restrict__ out,
    int gstart, int accumulate)
{
    const int g   = gstart + blockIdx.z;
    const int cnt = (g < NEXP) ? g_cnt[g] : NT_TOK;
    const int m0  = blockIdx.y * 256;
    if (m0 >= cnt) return;
    const int n0  = blockIdx.x * 256;
    const float* Bsrc = (g < NEXP) ? (wdn + (size_t)g * FDIM * DIM) : sdn;
    const int rowbase = (g < NEXP) ? g_off[g] : NT_TOK;

#if HAS_TCGEN05
    extern __shared__ char smraw[];
    uint32_t sb  = (smem_u32(smraw) + 1023u) & ~1023u;
    const uint32_t MB0 = sb, MB1 = sb + 8, TP = sb + 16;
    const uint32_t BUF = sb + 1024;

    const int tid = threadIdx.x, wid = tid >> 5, lane = tid & 31;

    if (wid == 0) { TC_ALLOC(TP, 512); TC_RELINQ(); }
    if (tid == 0) { MBAR_INIT(MB0, 1); MBAR_INIT(MB1, 1); }
    __syncthreads();
    uint32_t tb;
    asm volatile("ld.shared.b32 %0, [%1];" : "=r"(tb) : "r"(TP));

    const int arow = tid >> 3;
    const int akc  = (tid & 7) * 4;
    const float* aptr[4];
#pragma unroll
    for (int j = 0; j < 4; j++) {
        int row = m0 + arow + 64 * j;
        int rr  = (row < cnt) ? row : 0;
        aptr[j] = g_H + (size_t)(rowbase + rr) * FDIM;
    }
    const int bn  = wid * 16 + (lane & 15);
    const int bk0 = (lane >> 4) * 4;
    const float* bptr = Bsrc + n0 + bn;

    float4 rA[4]; float rB[4][4];
#pragma unroll
    for (int j = 0; j < 4; j++) rA[j] = *(const float4*)(aptr[j] + akc);
#pragma unroll
    for (int i = 0; i < 4; i++)
#pragma unroll
        for (int d = 0; d < 4; d++) rB[i][d] = bptr[(size_t)(bk0 + 8 * i + d) * DIM];

    int ph0 = 0, ph1 = 0;
    const int T = FDIM / 32;
    for (int t = 0; t < T; t++) {
        const int buf = t & 1;
        const uint32_t Ab = BUF + buf * STAGE_BYTES;
        const uint32_t Bb = Ab + 32768;
        if (t >= 2) { if (buf == 0) { MBAR_WAIT(MB0, ph0); ph0 ^= 1; } else { MBAR_WAIT(MB1, ph1); ph1 ^= 1; } }
#pragma unroll
        for (int j = 0; j < 4; j++) {
            // g_H is pre-rounded tf32: no cvt needed
            uint32_t off = (uint32_t)((arow + 64 * j) * 128 + akc * 4);
            STS128(Ab + SW128(off), __float_as_uint(rA[j].x), __float_as_uint(rA[j].y),
                                    __float_as_uint(rA[j].z), __float_as_uint(rA[j].w));
        }
#pragma unroll
        for (int i = 0; i < 4; i++) {
            uint32_t v0 = tf32u(rB[i][0]), v1 = tf32u(rB[i][1]);
            uint32_t v2 = tf32u(rB[i][2]), v3 = tf32u(rB[i][3]);
            uint32_t off = (uint32_t)(bn * 128 + (bk0 + 8 * i) * 4);
            STS128(Bb + SW128(off), v0, v1, v2, v3);
        }
        FENCE_ASYNC();
        __syncthreads();
        if (wid == 0 && elect_one()) {
            uint64_t dA0 = make_desc_sw128(Ab);
            uint64_t dA1 = make_desc_sw128(Ab + 16384);
            uint64_t dB  = make_desc_sw128(Bb);
#pragma unroll
            for (int c = 0; c < 4; c++) {
                uint32_t en = (t > 0 || c > 0) ? 1u : 0u;
                mma_tf32_ss(tb,       dA0 + c * 2, dB + c * 2, IDESC_TF32_M128_N256, en);
                mma_tf32_ss(tb + 256, dA1 + c * 2, dB + c * 2, IDESC_TF32_M128_N256, en);
            }
            TC_COMMIT(buf ? MB1 : MB0);
        }
        if (t + 1 < T) {
            int kb = (t + 1) * 32;
#pragma unroll
            for (int j = 0; j < 4; j++) rA[j] = *(const float4*)(aptr[j] + kb + akc);
#pragma unroll
            for (int i = 0; i < 4; i++)
#pragma unroll
                for (int d = 0; d < 4; d++) rB[i][d] = bptr[(size_t)(kb + bk0 + 8 * i + d) * DIM];
        }
    }
    { const int lb = (T - 1) & 1;
      if (lb == 0) { MBAR_WAIT(MB0, ph0); } else { MBAR_WAIT(MB1, ph1); } }
    TC_FENCE_AFTER();

    // ---- epilogue: scatter to out (routed: store; shared: add) ----
    const int mh = (wid >> 2) & 1, half = wid >> 3, subp = wid & 3;
    const int row = m0 + mh * 128 + subp * 32 + lane;
    const bool ok = row < cnt;
    int tok = 0;
    if (ok) tok = (g < NEXP) ? g_list[g * NT_TOK + row] : row;
    const size_t obase = (size_t)tok * DIM + n0 + half * 128;
#pragma unroll
    for (int c = 0; c < 4; c++) {
        uint32_t dr[32];
        uint32_t col = (uint32_t)(mh * 256 + half * 128 + c * 32);
        TC_LD_X32(dr, tb + col);
        TC_WAIT_LD();
        if (ok) {
            if (accumulate) {
#pragma unroll
                for (int q = 0; q < 8; q++) {
                    float4 o = *(float4*)&out[obase + c * 32 + q * 4];
                    o.x += __uint_as_float(dr[q*4]);   o.y += __uint_as_float(dr[q*4+1]);
                    o.z += __uint_as_float(dr[q*4+2]); o.w += __uint_as_float(dr[q*4+3]);
                    *(float4*)&out[obase + c * 32 + q * 4] = o;
                }
            } else {
#pragma unroll
                for (int q = 0; q < 8; q++)
                    *(float4*)&out[obase + c * 32 + q * 4] =
                        make_float4(__uint_as_float(dr[q*4]),   __uint_as_float(dr[q*4+1]),
                                    __uint_as_float(dr[q*4+2]), __uint_as_float(dr[q*4+3]));
            }
        }
    }
    __syncthreads();
    if (tid == 0) { MBAR_INVAL(MB0); MBAR_INVAL(MB1); }
    if (wid == 0) { TC_DEALLOC(tb, 512); }
#else
    // ---- portable fallback (compute_103 PTX pass; correct but naive) ----
    for (int idx = threadIdx.x; idx < 256 * 256; idx += 512) {
        int r  = idx >> 8;
        int cc = idx & 255;
        int row = m0 + r;
        if (row >= cnt) continue;
        const float* arow = g_H + (size_t)(rowbase + row) * FDIM;
        int col = n0 + cc;
        float s = 0.f;
        for (int k = 0; k < FDIM; k++)
            s += arow[k] * to_tf32(Bsrc[(size_t)k * DIM + col]);
        int tok = (g < NEXP) ? g_list[g * NT_TOK + row] : row;
        size_t o = (size_t)tok * DIM + col;
        if (accumulate) out[o] += s; else out[o] = s;
    }
#endif
}

// ---------------- launch ----------------
extern "C" void kernel_launch(void* const* d_in, const int* in_sizes, int n_in,
                              void* d_out, int out_size)
{
    const float* x   = (const float*)d_in[0];
    const float* rw  = (const float*)d_in[1];
    const float* wgu = (const float*)d_in[2];
    const float* wdn = (const float*)d_in[3];
    const float* sgu = (const float*)d_in[4];
    const float* sdn = (const float*)d_in[5];
    float* out = (float*)d_out;

    cudaFuncSetAttribute(gemm1_tc, cudaFuncAttributeMaxDynamicSharedMemorySize, SMEM_BYTES);
    cudaFuncSetAttribute(gemm2_tc, cudaFuncAttributeMaxDynamicSharedMemorySize, SMEM_BYTES);

    zero_kernel<<<1, 32>>>();
    router_kernel<<<NT_TOK / 8, 256>>>(x, rw);
    finalize_kernel<<<1, 1>>>();
    gemm1_tc<<<dim3(FDIM / 128, NT_TOK / 256, 9), 512, SMEM_BYTES>>>(x, wgu, sgu);
    // routed experts: exclusive plain stores (top-1)
    gemm2_tc<<<dim3(DIM / 256, NT_TOK / 256, NEXP), 512, SMEM_BYTES>>>(wdn, sdn, out, 0, 0);
    // shared MLP: read-add-store (stream-ordered after routed pass)
    gemm2_tc<<<dim3(DIM / 256, NT_TOK / 256, 1), 512, SMEM_BYTES>>>(wdn, sdn, out, 8, 1);
}

// round 10
// speedup vs baseline: 2.9899x; 1.1580x over previous
#include <cuda_runtime.h>
#include <cstdint>

#define NT_TOK 4096
#define DIM    2048
#define FDIM   4096
#define TWOF   8192
#define NEXP   8

// ---------------- static device scratch ----------------
__device__ int   g_cnt[9];
__device__ int   g_off[9];
__device__ int   g_list[NEXP * NT_TOK];
__device__ float g_gate[NEXP * NT_TOK];
// gathered gated input, rows [0,T) routed slots, [T,2T) shared tokens (tf32)
__device__ float g_X[2 * NT_TOK * (size_t)DIM];   // 64 MiB
// silu(gate)*up, same row space (tf32)
__device__ float g_H[2 * NT_TOK * (size_t)FDIM];  // 128 MiB

// ---------------- helpers (arch-neutral) ----------------
__device__ __forceinline__ float to_tf32(float x) {
    uint32_t u; asm("cvt.rna.tf32.f32 %0, %1;" : "=r"(u) : "f"(x));
    return __uint_as_float(u);
}
__device__ __forceinline__ uint32_t tf32u(float x) {
    uint32_t u; asm("cvt.rna.tf32.f32 %0, %1;" : "=r"(u) : "f"(x));
    return u;
}
__device__ __forceinline__ uint32_t smem_u32(const void* p) {
    uint32_t a;
    asm("{ .reg .u64 t; cvta.to.shared.u64 t, %1; cvt.u32.u64 %0, t; }" : "=r"(a) : "l"(p));
    return a;
}
#define SW128(o) ((o) ^ (((o) >> 3) & 0x70))

#if defined(__CUDA_ARCH__) && defined(__CUDA_ARCH_FEAT_SM103_ALL)
#define HAS_TCGEN05 1
#else
#define HAS_TCGEN05 0
#endif

#if HAS_TCGEN05
__device__ __forceinline__ uint32_t elect_one() {
    uint32_t p;
    asm volatile("{\n\t.reg .pred p;\n\telect.sync _|p, 0xFFFFFFFF;\n\t"
                 "selp.b32 %0, 1, 0, p;\n\t}" : "=r"(p));
    return p;
}
static __device__ __forceinline__ uint64_t make_desc_sw128(uint32_t addr) {
    const uint64_t base =
        (uint64_t(2) << 61) | (uint64_t(1) << 46) | (uint64_t(64) << 32) | (uint64_t(1) << 16);
    return base | ((uint64_t)(addr >> 4) & 0x3FFF);
}
#define IDESC_TF32_M128_N256 ((1u<<4)|(2u<<7)|(2u<<10)|((256u/8)<<17)|((128u/16)<<24))

__device__ __forceinline__ void mma_tf32_ss(uint32_t d, uint64_t da, uint64_t db,
                                            uint32_t idesc, uint32_t en) {
    asm volatile(
        "{\n\t.reg .pred p;\n\tsetp.ne.u32 p, %4, 0;\n\t"
        "tcgen05.mma.cta_group::1.kind::tf32 [%0], %1, %2, %3, {%5, %5, %5, %5}, p;\n\t}"
        :: "r"(d), "l"(da), "l"(db), "r"(idesc), "r"(en), "r"(0u) : "memory");
}

#define TC_ALLOC(sm, n)   asm volatile("tcgen05.alloc.cta_group::1.sync.aligned.shared::cta.b32 [%0], %1;" :: "r"(sm), "r"(n) : "memory")
#define TC_DEALLOC(tb, n) asm volatile("tcgen05.dealloc.cta_group::1.sync.aligned.b32 %0, %1;" :: "r"(tb), "r"(n))
#define TC_RELINQ()       asm volatile("tcgen05.relinquish_alloc_permit.cta_group::1.sync.aligned;")
#define TC_COMMIT(mb)     asm volatile("tcgen05.commit.cta_group::1.mbarrier::arrive::one.shared::cluster.b64 [%0];" :: "r"(mb) : "memory")
#define TC_FENCE_AFTER()  asm volatile("tcgen05.fence::after_thread_sync;" ::: "memory")
#define TC_WAIT_LD()      asm volatile("tcgen05.wait::ld.sync.aligned;" ::: "memory")
#define FENCE_ASYNC()     asm volatile("fence.proxy.async.shared::cta;" ::: "memory")
#define MBAR_INIT(mb, c)  asm volatile("mbarrier.init.shared.b64 [%0], %1;" :: "r"(mb), "r"(c) : "memory")
#define MBAR_INVAL(mb)    asm volatile("mbarrier.inval.shared.b64 [%0];" :: "r"(mb) : "memory")

#define MBAR_WAIT(mb, ph) do {                                                       \
    uint32_t _m = (mb); uint32_t _p = (ph); uint32_t _d;                             \
    asm volatile("{\n\t.reg .pred p;\n\t"                                            \
        "mbarrier.try_wait.parity.acquire.cta.shared::cta.b64 p, [%1], %2;\n\t"      \
        "selp.b32 %0, 1, 0, p;\n\t}" : "=r"(_d) : "r"(_m), "r"(_p) : "memory");      \
    if (!_d) {                                                                       \
        asm volatile("{\n\t.reg .pred P1;\n\tWL_%=:\n\t"                             \
            "mbarrier.try_wait.parity.acquire.cta.shared::cta.b64 P1, [%0], %1, 0x989680;\n\t" \
            "@P1 bra.uni WD_%=;\n\tbra.uni WL_%=;\n\tWD_%=:\n\t}"                    \
            :: "r"(_m), "r"(_p) : "memory");                                         \
    }                                                                                \
} while (0)

#define TC_LD_X32(r, addr)                                                           \
    asm volatile("tcgen05.ld.sync.aligned.32x32b.x32.b32 "                           \
        "{%0,%1,%2,%3,%4,%5,%6,%7,%8,%9,%10,%11,%12,%13,%14,%15,"                    \
        "%16,%17,%18,%19,%20,%21,%22,%23,%24,%25,%26,%27,%28,%29,%30,%31}, [%32];"   \
        : "=r"((r)[0]),"=r"((r)[1]),"=r"((r)[2]),"=r"((r)[3]),                       \
          "=r"((r)[4]),"=r"((r)[5]),"=r"((r)[6]),"=r"((r)[7]),                       \
          "=r"((r)[8]),"=r"((r)[9]),"=r"((r)[10]),"=r"((r)[11]),                     \
          "=r"((r)[12]),"=r"((r)[13]),"=r"((r)[14]),"=r"((r)[15]),                   \
          "=r"((r)[16]),"=r"((r)[17]),"=r"((r)[18]),"=r"((r)[19]),                   \
          "=r"((r)[20]),"=r"((r)[21]),"=r"((r)[22]),"=r"((r)[23]),                   \
          "=r"((r)[24]),"=r"((r)[25]),"=r"((r)[26]),"=r"((r)[27]),                   \
          "=r"((r)[28]),"=r"((r)[29]),"=r"((r)[30]),"=r"((r)[31])                    \
        : "r"(addr))

#define STS128(addr, a, b, c, d)                                                     \
    asm volatile("st.shared.v4.b32 [%0], {%1, %2, %3, %4};"                          \
                 :: "r"(addr), "r"(a), "r"(b), "r"(c), "r"(d) : "memory")
__device__ __forceinline__ void cp16(uint32_t dst, const void* src) {
    asm volatile("cp.async.cg.shared.global [%0], [%1], 16;\n" :: "r"(dst), "l"(src));
}
#define CP_COMMIT() asm volatile("cp.async.commit_group;\n")
#define CP_WAIT1()  asm volatile("cp.async.wait_group 1;\n")
#endif  // HAS_TCGEN05

// 3-stage pipeline: stage = A(32KB) + B(32KB)
#define STAGE_BYTES 65536
#define NSTAGE 3
#define SMEM_BYTES (2048 + NSTAGE * STAGE_BYTES)

// ---------------- router ----------------
__global__ void zero_kernel() { if (threadIdx.x < 9) g_cnt[threadIdx.x] = 0; }

__global__ __launch_bounds__(256) void router_kernel(
    const float* __restrict__ x, const float* __restrict__ rw)
{
    int t = blockIdx.x * 8 + (threadIdx.x >> 5);
    int lane = threadIdx.x & 31;
    const float* xr = x + (size_t)t * DIM;
    float p[8];
#pragma unroll
    for (int e = 0; e < 8; e++) p[e] = 0.f;
    for (int k = lane; k < DIM; k += 32) {
        float xv = xr[k];
#pragma unroll
        for (int e = 0; e < 8; e++) p[e] += xv * rw[e * DIM + k];
    }
#pragma unroll
    for (int e = 0; e < 8; e++)
#pragma unroll
        for (int o = 16; o > 0; o >>= 1) p[e] += __shfl_xor_sync(~0u, p[e], o);
    if (lane == 0) {
        float best = p[0]; int bi = 0;
#pragma unroll
        for (int e = 1; e < 8; e++) if (p[e] > best) { best = p[e]; bi = e; }
        float gate = 1.0f / (1.0f + expf(-best));
        int pos = atomicAdd(&g_cnt[bi], 1);
        g_list[bi * NT_TOK + pos] = t;
        g_gate[bi * NT_TOK + pos] = gate;
    }
}

__global__ void finalize_kernel() {
    int o = 0;
    for (int e = 0; e < 8; e++) { g_off[e] = o; o += g_cnt[e]; }
    g_off[8] = NT_TOK;
}

// ---------------- gather: g_X[slot] = tf32(gate * x[tok]) ----------------
__global__ __launch_bounds__(256) void gather_kernel(const float* __restrict__ x)
{
    int row = blockIdx.x;  // 0..2T-1
    int tok; float gate;
    if (row < NT_TOK) {
        int e = 0;
#pragma unroll
        for (int i = 1; i < 8; i++) if (row >= g_off[i]) e = i;
        int idx = row - g_off[e];
        tok  = g_list[e * NT_TOK + idx];
        gate = g_gate[e * NT_TOK + idx];
    } else { tok = row - NT_TOK; gate = 1.f; }
    const float4* src = (const float4*)(x + (size_t)tok * DIM);
    float4* dst = (float4*)(g_X + (size_t)row * DIM);
    for (int j = threadIdx.x; j < DIM / 4; j += 256) {
        float4 v = src[j];
        v.x = to_tf32(v.x * gate); v.y = to_tf32(v.y * gate);
        v.z = to_tf32(v.z * gate); v.w = to_tf32(v.w * gate);
        dst[j] = v;
    }
}

// ================= GEMM1: H = silu(Xg@Wg) * (Xg@Wu) =================
// M=256 slots x (128 gate | 128 up). grid: (FDIM/128, NT_TOK/256, 9), block 512.
__global__ __launch_bounds__(512, 1) void gemm1_tc(
    const float* __restrict__ wgu,
    const float* __restrict__ sgu)
{
    const int g   = blockIdx.z;
    const int cnt = (g < NEXP) ? g_cnt[g] : NT_TOK;
    const int m0  = blockIdx.y * 256;
    if (m0 >= cnt) return;
    const int hb  = blockIdx.x;
    const float* Bsrc = (g < NEXP) ? (wgu + (size_t)g * DIM * TWOF) : sgu;
    const int rowbase = (g < NEXP) ? g_off[g] : NT_TOK;

#if HAS_TCGEN05
    extern __shared__ char smraw[];
    uint32_t sb = (smem_u32(smraw) + 1023u) & ~1023u;
    const uint32_t MB0 = sb, MB1 = sb + 8, MB2 = sb + 16, TP = sb + 24;
    const uint32_t BUF = sb + 1024;

    const int tid = threadIdx.x, wid = tid >> 5, lane = tid & 31;

    if (wid == 0) { TC_ALLOC(TP, 512); TC_RELINQ(); }
    if (tid == 0) { MBAR_INIT(MB0, 1); MBAR_INIT(MB1, 1); MBAR_INIT(MB2, 1); }
    __syncthreads();
    uint32_t tb;
    asm volatile("ld.shared.b32 %0, [%1];" : "=r"(tb) : "r"(TP));

    // A: contiguous slot rows from g_X via cp.async
    const int ar  = tid >> 3;          // 64 row groups
    const int akc = (tid & 7) * 4;     // k offset (floats)
    const float* abase = g_X + (size_t)(rowbase + m0) * DIM;
    uint32_t aoff[4];
#pragma unroll
    for (int j = 0; j < 4; j++)
        aoff[j] = SW128((uint32_t)((ar + 64 * j) * 128 + akc * 4));

    // B: strided scalar loads (register prefetch), STS128 per 4 consecutive k
    const int bn  = wid * 16 + (lane & 15);   // n in [0,256)
    const int bk0 = (lane >> 4) * 4;          // k subgroup 0 or 4
    const int gcol = (bn < 128) ? (hb * 128 + bn) : (FDIM + hb * 128 + bn - 128);
    const float* bptr = Bsrc + (size_t)bk0 * TWOF + gcol;
    uint32_t boff[4];
#pragma unroll
    for (int i = 0; i < 4; i++)
        boff[i] = SW128((uint32_t)(bn * 128 + (bk0 + 8 * i) * 4));

    float rB[4][4];
#pragma unroll
    for (int i = 0; i < 4; i++)
#pragma unroll
        for (int d = 0; d < 4; d++) rB[i][d] = bptr[(size_t)(8 * i + d) * TWOF];

    // bootstrap A stage 0
    {
        uint32_t Ab = BUF;
#pragma unroll
        for (int j = 0; j < 4; j++)
            cp16(Ab + aoff[j], abase + (size_t)(ar + 64 * j) * DIM + akc);
        CP_COMMIT();
    }

    int p0 = 0, p1 = 0, p2 = 0;
    const int T = DIM / 32;
    for (int t = 0; t < T; t++) {
        const int s  = t % 3;
        const int sn = (t + 1) % 3;
        const uint32_t Ab  = BUF + (uint32_t)s * STAGE_BYTES;
        const uint32_t Bb  = Ab + 32768;
        if (t >= 2) {
            if      (sn == 0) { MBAR_WAIT(MB0, p0); p0 ^= 1; }
            else if (sn == 1) { MBAR_WAIT(MB1, p1); p1 ^= 1; }
            else              { MBAR_WAIT(MB2, p2); p2 ^= 1; }
        }
        if (t + 1 < T) {
            uint32_t An = BUF + (uint32_t)sn * STAGE_BYTES;
            const float* asrc = abase + (t + 1) * 32 + akc;
#pragma unroll
            for (int j = 0; j < 4; j++)
                cp16(An + aoff[j], asrc + (size_t)(ar + 64 * j) * DIM);
        }
        CP_COMMIT();
        CP_WAIT1();   // A for stage s complete
#pragma unroll
        for (int i = 0; i < 4; i++)
            STS128(Bb + boff[i], tf32u(rB[i][0]), tf32u(rB[i][1]),
                                 tf32u(rB[i][2]), tf32u(rB[i][3]));
        FENCE_ASYNC();
        __syncthreads();
        if (wid == 0 && elect_one()) {
            uint64_t dA0 = make_desc_sw128(Ab);
            uint64_t dA1 = make_desc_sw128(Ab + 16384);
            uint64_t dB  = make_desc_sw128(Bb);
#pragma unroll
            for (int c = 0; c < 4; c++) {
                uint32_t en = (t > 0 || c > 0) ? 1u : 0u;
                mma_tf32_ss(tb,       dA0 + c * 2, dB + c * 2, IDESC_TF32_M128_N256, en);
                mma_tf32_ss(tb + 256, dA1 + c * 2, dB + c * 2, IDESC_TF32_M128_N256, en);
            }
            TC_COMMIT(s == 0 ? MB0 : (s == 1 ? MB1 : MB2));
        }
        if (t + 1 < T) {
            const float* bsrc = bptr + (size_t)(t + 1) * 32 * TWOF;
#pragma unroll
            for (int i = 0; i < 4; i++)
#pragma unroll
                for (int d = 0; d < 4; d++) rB[i][d] = bsrc[(size_t)(8 * i + d) * TWOF];
        }
    }
    { const int sf = (T - 1) % 3;
      if      (sf == 0) MBAR_WAIT(MB0, p0);
      else if (sf == 1) MBAR_WAIT(MB1, p1);
      else              MBAR_WAIT(MB2, p2); }
    TC_FENCE_AFTER();

    // ---- epilogue: silu(g)*u -> g_H ----
    const int mh = (wid >> 2) & 1, half = wid >> 3, subp = wid & 3;
    const int row = m0 + mh * 128 + subp * 32 + lane;
    const bool ok = row < cnt;
    const size_t hbase = (size_t)(rowbase + row) * FDIM + hb * 128 + half * 64;
#pragma unroll
    for (int c = 0; c < 2; c++) {
        uint32_t gr[32], ur[32];
        uint32_t col = (uint32_t)(mh * 256 + half * 64 + c * 32);
        TC_LD_X32(gr, tb + col);
        TC_LD_X32(ur, tb + col + 128);
        TC_WAIT_LD();
        if (ok) {
            float h[32];
#pragma unroll
            for (int r = 0; r < 32; r++) {
                float gv = __uint_as_float(gr[r]), uv = __uint_as_float(ur[r]);
                h[r] = to_tf32(gv / (1.f + expf(-gv)) * uv);
            }
#pragma unroll
            for (int q = 0; q < 8; q++)
                *(float4*)&g_H[hbase + c * 32 + q * 4] =
                    make_float4(h[q*4], h[q*4+1], h[q*4+2], h[q*4+3]);
        }
    }
    __syncthreads();
    if (tid == 0) { MBAR_INVAL(MB0); MBAR_INVAL(MB1); MBAR_INVAL(MB2); }
    if (wid == 0) { TC_DEALLOC(tb, 512); }
#else
    // portable fallback (compute_103 pass)
    for (int idx = threadIdx.x; idx < 256 * 128; idx += 512) {
        int r = idx >> 7, cc = idx & 127;
        int row = m0 + r;
        if (row >= cnt) continue;
        const float* arow = g_X + (size_t)(rowbase + row) * DIM;
        int col = hb * 128 + cc;
        float sg = 0.f, su = 0.f;
        for (int k = 0; k < DIM; k++) {
            float a = arow[k];
            sg += a * to_tf32(Bsrc[(size_t)k * TWOF + col]);
            su += a * to_tf32(Bsrc[(size_t)k * TWOF + FDIM + col]);
        }
        g_H[(size_t)(rowbase + row) * FDIM + col] = to_tf32(sg / (1.f + expf(-sg)) * su);
    }
#endif
}

// ================= GEMM2: out (+)= H @ Wdn =================
// M=256 slots x N=256 cols. grid: (DIM/256, NT_TOK/256, nz), block 512.
__global__ __launch_bounds__(512, 1) void gemm2_tc(
    const float* __restrict__ wdn,
    const float* __restrict__ sdn,
    float* __restrict__ out,
    int gstart, int accumulate)
{
    const int g   = gstart + blockIdx.z;
    const int cnt = (g < NEXP) ? g_cnt[g] : NT_TOK;
    const int m0  = blockIdx.y * 256;
    if (m0 >= cnt) return;
    const int n0  = blockIdx.x * 256;
    const float* Bsrc = (g < NEXP) ? (wdn + (size_t)g * FDIM * DIM) : sdn;
    const int rowbase = (g < NEXP) ? g_off[g] : NT_TOK;

#if HAS_TCGEN05
    extern __shared__ char smraw[];
    uint32_t sb = (smem_u32(smraw) + 1023u) & ~1023u;
    const uint32_t MB0 = sb, MB1 = sb + 8, MB2 = sb + 16, TP = sb + 24;
    const uint32_t BUF = sb + 1024;

    const int tid = threadIdx.x, wid = tid >> 5, lane = tid & 31;

    if (wid == 0) { TC_ALLOC(TP, 512); TC_RELINQ(); }
    if (tid == 0) { MBAR_INIT(MB0, 1); MBAR_INIT(MB1, 1); MBAR_INIT(MB2, 1); }
    __syncthreads();
    uint32_t tb;
    asm volatile("ld.shared.b32 %0, [%1];" : "=r"(tb) : "r"(TP));

    const int ar  = tid >> 3;
    const int akc = (tid & 7) * 4;
    const float* abase = g_H + (size_t)(rowbase + m0) * FDIM;
    uint32_t aoff[4];
#pragma unroll
    for (int j = 0; j < 4; j++)
        aoff[j] = SW128((uint32_t)((ar + 64 * j) * 128 + akc * 4));

    const int bn  = wid * 16 + (lane & 15);
    const int bk0 = (lane >> 4) * 4;
    const float* bptr = Bsrc + (size_t)bk0 * DIM + n0 + bn;
    uint32_t boff[4];
#pragma unroll
    for (int i = 0; i < 4; i++)
        boff[i] = SW128((uint32_t)(bn * 128 + (bk0 + 8 * i) * 4));

    float rB[4][4];
#pragma unroll
    for (int i = 0; i < 4; i++)
#pragma unroll
        for (int d = 0; d < 4; d++) rB[i][d] = bptr[(size_t)(8 * i + d) * DIM];

    {
        uint32_t Ab = BUF;
#pragma unroll
        for (int j = 0; j < 4; j++)
            cp16(Ab + aoff[j], abase + (size_t)(ar + 64 * j) * FDIM + akc);
        CP_COMMIT();
    }

    int p0 = 0, p1 = 0, p2 = 0;
    const int T = FDIM / 32;
    for (int t = 0; t < T; t++) {
        const int s  = t % 3;
        const int sn = (t + 1) % 3;
        const uint32_t Ab = BUF + (uint32_t)s * STAGE_BYTES;
        const uint32_t Bb = Ab + 32768;
        if (t >= 2) {
            if      (sn == 0) { MBAR_WAIT(MB0, p0); p0 ^= 1; }
            else if (sn == 1) { MBAR_WAIT(MB1, p1); p1 ^= 1; }
            else              { MBAR_WAIT(MB2, p2); p2 ^= 1; }
        }
        if (t + 1 < T) {
            uint32_t An = BUF + (uint32_t)sn * STAGE_BYTES;
            const float* asrc = abase + (t + 1) * 32 + akc;
#pragma unroll
            for (int j = 0; j < 4; j++)
                cp16(An + aoff[j], asrc + (size_t)(ar + 64 * j) * FDIM);
        }
        CP_COMMIT();
        CP_WAIT1();
#pragma unroll
        for (int i = 0; i < 4; i++)
            STS128(Bb + boff[i], tf32u(rB[i][0]), tf32u(rB[i][1]),
                                 tf32u(rB[i][2]), tf32u(rB[i][3]));
        FENCE_ASYNC();
        __syncthreads();
        if (wid == 0 && elect_one()) {
            uint64_t dA0 = make_desc_sw128(Ab);
            uint64_t dA1 = make_desc_sw128(Ab + 16384);
            uint64_t dB  = make_desc_sw128(Bb);
#pragma unroll
            for (int c = 0; c < 4; c++) {
                uint32_t en = (t > 0 || c > 0) ? 1u : 0u;
                mma_tf32_ss(tb,       dA0 + c * 2, dB + c * 2, IDESC_TF32_M128_N256, en);
                mma_tf32_ss(tb + 256, dA1 + c * 2, dB + c * 2, IDESC_TF32_M128_N256, en);
            }
            TC_COMMIT(s == 0 ? MB0 : (s == 1 ? MB1 : MB2));
        }
        if (t + 1 < T) {
            const float* bsrc = bptr + (size_t)(t + 1) * 32 * DIM;
#pragma unroll
            for (int i = 0; i < 4; i++)
#pragma unroll
                for (int d = 0; d < 4; d++) rB[i][d] = bsrc[(size_t)(8 * i + d) * DIM];
        }
    }
    { const int sf = (T - 1) % 3;
      if      (sf == 0) MBAR_WAIT(MB0, p0);
      else if (sf == 1) MBAR_WAIT(MB1, p1);
      else              MBAR_WAIT(MB2, p2); }
    TC_FENCE_AFTER();

    // ---- epilogue: scatter (routed: store; shared: add) ----
    const int mh = (wid >> 2) & 1, half = wid >> 3, subp = wid & 3;
    const int row = m0 + mh * 128 + subp * 32 + lane;
    const bool ok = row < cnt;
    int tok = 0;
    if (ok) tok = (g < NEXP) ? g_list[g * NT_TOK + row] : row;
    const size_t obase = (size_t)tok * DIM + n0 + half * 128;
#pragma unroll
    for (int c = 0; c < 4; c++) {
        uint32_t dr[32];
        uint32_t col = (uint32_t)(mh * 256 + half * 128 + c * 32);
        TC_LD_X32(dr, tb + col);
        TC_WAIT_LD();
        if (ok) {
            if (accumulate) {
#pragma unroll
                for (int q = 0; q < 8; q++) {
                    float4 o = *(float4*)&out[obase + c * 32 + q * 4];
                    o.x += __uint_as_float(dr[q*4]);   o.y += __uint_as_float(dr[q*4+1]);
                    o.z += __uint_as_float(dr[q*4+2]); o.w += __uint_as_float(dr[q*4+3]);
                    *(float4*)&out[obase + c * 32 + q * 4] = o;
                }
            } else {
#pragma unroll
                for (int q = 0; q < 8; q++)
                    *(float4*)&out[obase + c * 32 + q * 4] =
                        make_float4(__uint_as_float(dr[q*4]),   __uint_as_float(dr[q*4+1]),
                                    __uint_as_float(dr[q*4+2]), __uint_as_float(dr[q*4+3]));
            }
        }
    }
    __syncthreads();
    if (tid == 0) { MBAR_INVAL(MB0); MBAR_INVAL(MB1); MBAR_INVAL(MB2); }
    if (wid == 0) { TC_DEALLOC(tb, 512); }
#else
    // portable fallback (compute_103 pass)
    for (int idx = threadIdx.x; idx < 256 * 256; idx += 512) {
        int r = idx >> 8, cc = idx & 255;
        int row = m0 + r;
        if (row >= cnt) continue;
        const float* arow = g_H + (size_t)(rowbase + row) * FDIM;
        int col = n0 + cc;
        float s = 0.f;
        for (int k = 0; k < FDIM; k++)
            s += arow[k] * to_tf32(Bsrc[(size_t)k * DIM + col]);
        int tok = (g < NEXP) ? g_list[g * NT_TOK + row] : row;
        size_t o = (size_t)tok * DIM + col;
        if (accumulate) out[o] += s; else out[o] = s;
    }
#endif
}

// ---------------- launch ----------------
extern "C" void kernel_launch(void* const* d_in, const int* in_sizes, int n_in,
                              void* d_out, int out_size)
{
    const float* x   = (const float*)d_in[0];
    const float* rw  = (const float*)d_in[1];
    const float* wgu = (const float*)d_in[2];
    const float* wdn = (const float*)d_in[3];
    const float* sgu = (const float*)d_in[4];
    const float* sdn = (const float*)d_in[5];
    float* out = (float*)d_out;

    cudaFuncSetAttribute(gemm1_tc, cudaFuncAttributeMaxDynamicSharedMemorySize, SMEM_BYTES);
    cudaFuncSetAttribute(gemm2_tc, cudaFuncAttributeMaxDynamicSharedMemorySize, SMEM_BYTES);

    zero_kernel<<<1, 32>>>();
    router_kernel<<<NT_TOK / 8, 256>>>(x, rw);
    finalize_kernel<<<1, 1>>>();
    gather_kernel<<<2 * NT_TOK, 256>>>(x);
    gemm1_tc<<<dim3(FDIM / 128, NT_TOK / 256, 9), 512, SMEM_BYTES>>>(wgu, sgu);
    gemm2_tc<<<dim3(DIM / 256, NT_TOK / 256, NEXP), 512, SMEM_BYTES>>>(wdn, sdn, out, 0, 0);
    gemm2_tc<<<dim3(DIM / 256, NT_TOK / 256, 1), 512, SMEM_BYTES>>>(wdn, sdn, out, 8, 1);
}

// round 11
// speedup vs baseline: 3.4045x; 1.1387x over previous
#include <cuda_runtime.h>
#include <cstdint>

#define NT_TOK 4096
#define DIM    2048
#define FDIM   4096
#define TWOF   8192
#define NEXP   8

// ---------------- static device scratch ----------------
__device__ int   g_cnt[9];
__device__ int   g_off[9];
__device__ int   g_list[NEXP * NT_TOK];
__device__ float g_gate[NEXP * NT_TOK];
// gathered gated input, rows [0,T) routed slots, [T,2T) shared tokens (tf32)
__device__ float g_X[2 * NT_TOK * (size_t)DIM];   // 64 MiB
// silu(gate)*up, same row space (tf32)
__device__ float g_H[2 * NT_TOK * (size_t)FDIM];  // 128 MiB

// ---------------- helpers (arch-neutral) ----------------
__device__ __forceinline__ float to_tf32(float x) {
    uint32_t u; asm("cvt.rna.tf32.f32 %0, %1;" : "=r"(u) : "f"(x));
    return __uint_as_float(u);
}
__device__ __forceinline__ uint32_t tf32u(float x) {
    uint32_t u; asm("cvt.rna.tf32.f32 %0, %1;" : "=r"(u) : "f"(x));
    return u;
}
__device__ __forceinline__ uint32_t smem_u32(const void* p) {
    uint32_t a;
    asm("{ .reg .u64 t; cvta.to.shared.u64 t, %1; cvt.u32.u64 %0, t; }" : "=r"(a) : "l"(p));
    return a;
}
#define SW128(o) ((o) ^ (((o) >> 3) & 0x70))

#if defined(__CUDA_ARCH__) && defined(__CUDA_ARCH_FEAT_SM103_ALL)
#define HAS_TCGEN05 1
#else
#define HAS_TCGEN05 0
#endif

#if HAS_TCGEN05
__device__ __forceinline__ uint32_t elect_one() {
    uint32_t p;
    asm volatile("{\n\t.reg .pred p;\n\telect.sync _|p, 0xFFFFFFFF;\n\t"
                 "selp.b32 %0, 1, 0, p;\n\t}" : "=r"(p));
    return p;
}
static __device__ __forceinline__ uint64_t make_desc_sw128(uint32_t addr) {
    const uint64_t base =
        (uint64_t(2) << 61) | (uint64_t(1) << 46) | (uint64_t(64) << 32) | (uint64_t(1) << 16);
    return base | ((uint64_t)(addr >> 4) & 0x3FFF);
}
#define IDESC_TF32_M128_N256 ((1u<<4)|(2u<<7)|(2u<<10)|((256u/8)<<17)|((128u/16)<<24))

__device__ __forceinline__ void mma_tf32_ss(uint32_t d, uint64_t da, uint64_t db,
                                            uint32_t idesc, uint32_t en) {
    asm volatile(
        "{\n\t.reg .pred p;\n\tsetp.ne.u32 p, %4, 0;\n\t"
        "tcgen05.mma.cta_group::1.kind::tf32 [%0], %1, %2, %3, {%5, %5, %5, %5}, p;\n\t}"
        :: "r"(d), "l"(da), "l"(db), "r"(idesc), "r"(en), "r"(0u) : "memory");
}

#define TC_ALLOC(sm, n)   asm volatile("tcgen05.alloc.cta_group::1.sync.aligned.shared::cta.b32 [%0], %1;" :: "r"(sm), "r"(n) : "memory")
#define TC_DEALLOC(tb, n) asm volatile("tcgen05.dealloc.cta_group::1.sync.aligned.b32 %0, %1;" :: "r"(tb), "r"(n))
#define TC_RELINQ()       asm volatile("tcgen05.relinquish_alloc_permit.cta_group::1.sync.aligned;")
#define TC_COMMIT(mb)     asm volatile("tcgen05.commit.cta_group::1.mbarrier::arrive::one.shared::cluster.b64 [%0];" :: "r"(mb) : "memory")
#define TC_FENCE_AFTER()  asm volatile("tcgen05.fence::after_thread_sync;" ::: "memory")
#define TC_WAIT_LD()      asm volatile("tcgen05.wait::ld.sync.aligned;" ::: "memory")
#define FENCE_ASYNC()     asm volatile("fence.proxy.async.shared::cta;" ::: "memory")
#define MBAR_INIT(mb, c)  asm volatile("mbarrier.init.shared.b64 [%0], %1;" :: "r"(mb), "r"(c) : "memory")
#define MBAR_INVAL(mb)    asm volatile("mbarrier.inval.shared.b64 [%0];" :: "r"(mb) : "memory")
#define MBAR_ARRIVE(mb)   asm volatile("mbarrier.arrive.shared.b64 _, [%0];" :: "r"(mb) : "memory")

#define MBAR_WAIT(mb, ph) do {                                                       \
    uint32_t _m = (mb); uint32_t _p = (ph); uint32_t _d;                             \
    asm volatile("{\n\t.reg .pred p;\n\t"                                            \
        "mbarrier.try_wait.parity.acquire.cta.shared::cta.b64 p, [%1], %2;\n\t"      \
        "selp.b32 %0, 1, 0, p;\n\t}" : "=r"(_d) : "r"(_m), "r"(_p) : "memory");      \
    if (!_d) {                                                                       \
        asm volatile("{\n\t.reg .pred P1;\n\tWL_%=:\n\t"                             \
            "mbarrier.try_wait.parity.acquire.cta.shared::cta.b64 P1, [%0], %1, 0x989680;\n\t" \
            "@P1 bra.uni WD_%=;\n\tbra.uni WL_%=;\n\tWD_%=:\n\t}"                    \
            :: "r"(_m), "r"(_p) : "memory");                                         \
    }                                                                                \
} while (0)

#define TC_LD_X32(r, addr)                                                           \
    asm volatile("tcgen05.ld.sync.aligned.32x32b.x32.b32 "                           \
        "{%0,%1,%2,%3,%4,%5,%6,%7,%8,%9,%10,%11,%12,%13,%14,%15,"                    \
        "%16,%17,%18,%19,%20,%21,%22,%23,%24,%25,%26,%27,%28,%29,%30,%31}, [%32];"   \
        : "=r"((r)[0]),"=r"((r)[1]),"=r"((r)[2]),"=r"((r)[3]),                       \
          "=r"((r)[4]),"=r"((r)[5]),"=r"((r)[6]),"=r"((r)[7]),                       \
          "=r"((r)[8]),"=r"((r)[9]),"=r"((r)[10]),"=r"((r)[11]),                     \
          "=r"((r)[12]),"=r"((r)[13]),"=r"((r)[14]),"=r"((r)[15]),                   \
          "=r"((r)[16]),"=r"((r)[17]),"=r"((r)[18]),"=r"((r)[19]),                   \
          "=r"((r)[20]),"=r"((r)[21]),"=r"((r)[22]),"=r"((r)[23]),                   \
          "=r"((r)[24]),"=r"((r)[25]),"=r"((r)[26]),"=r"((r)[27]),                   \
          "=r"((r)[28]),"=r"((r)[29]),"=r"((r)[30]),"=r"((r)[31])                    \
        : "r"(addr))

#define STS128(addr, a, b, c, d)                                                     \
    asm volatile("st.shared.v4.b32 [%0], {%1, %2, %3, %4};"                          \
                 :: "r"(addr), "r"(a), "r"(b), "r"(c), "r"(d) : "memory")
#endif  // HAS_TCGEN05

// 3-stage ring: stage = A(32KB) + B(32KB)
#define STAGE_BYTES 65536
#define NSTAGE 3
#define SMEM_BYTES (2048 + NSTAGE * STAGE_BYTES)
#define NTHREADS 544           // 16 producer warps + 1 MMA warp

// ---------------- router ----------------
__global__ void zero_kernel() { if (threadIdx.x < 9) g_cnt[threadIdx.x] = 0; }

__global__ __launch_bounds__(256) void router_kernel(
    const float* __restrict__ x, const float* __restrict__ rw)
{
    int t = blockIdx.x * 8 + (threadIdx.x >> 5);
    int lane = threadIdx.x & 31;
    const float* xr = x + (size_t)t * DIM;
    float p[8];
#pragma unroll
    for (int e = 0; e < 8; e++) p[e] = 0.f;
    for (int k = lane; k < DIM; k += 32) {
        float xv = xr[k];
#pragma unroll
        for (int e = 0; e < 8; e++) p[e] += xv * rw[e * DIM + k];
    }
#pragma unroll
    for (int e = 0; e < 8; e++)
#pragma unroll
        for (int o = 16; o > 0; o >>= 1) p[e] += __shfl_xor_sync(~0u, p[e], o);
    if (lane == 0) {
        float best = p[0]; int bi = 0;
#pragma unroll
        for (int e = 1; e < 8; e++) if (p[e] > best) { best = p[e]; bi = e; }
        float gate = 1.0f / (1.0f + expf(-best));
        int pos = atomicAdd(&g_cnt[bi], 1);
        g_list[bi * NT_TOK + pos] = t;
        g_gate[bi * NT_TOK + pos] = gate;
    }
}

__global__ void finalize_kernel() {
    int o = 0;
    for (int e = 0; e < 8; e++) { g_off[e] = o; o += g_cnt[e]; }
    g_off[8] = NT_TOK;
}

// ---------------- gather: g_X[slot] = tf32(gate * x[tok]) ----------------
__global__ __launch_bounds__(256) void gather_kernel(const float* __restrict__ x)
{
    int row = blockIdx.x;  // 0..2T-1
    int tok; float gate;
    if (row < NT_TOK) {
        int e = 0;
#pragma unroll
        for (int i = 1; i < 8; i++) if (row >= g_off[i]) e = i;
        int idx = row - g_off[e];
        tok  = g_list[e * NT_TOK + idx];
        gate = g_gate[e * NT_TOK + idx];
    } else { tok = row - NT_TOK; gate = 1.f; }
    const float4* src = (const float4*)(x + (size_t)tok * DIM);
    float4* dst = (float4*)(g_X + (size_t)row * DIM);
    for (int j = threadIdx.x; j < DIM / 4; j += 256) {
        float4 v = src[j];
        v.x = to_tf32(v.x * gate); v.y = to_tf32(v.y * gate);
        v.z = to_tf32(v.z * gate); v.w = to_tf32(v.w * gate);
        dst[j] = v;
    }
}

// ================= GEMM1: H = silu(Xg@Wg) * (Xg@Wu) =================
// M=256 slots x (128 gate | 128 up). grid: (FDIM/128, NT_TOK/256, 9), block 544.
__global__ __launch_bounds__(NTHREADS, 1) void gemm1_tc(
    const float* __restrict__ wgu,
    const float* __restrict__ sgu)
{
    const int g   = blockIdx.z;
    const int cnt = (g < NEXP) ? g_cnt[g] : NT_TOK;
    const int m0  = blockIdx.y * 256;
    if (m0 >= cnt) return;
    const int hb  = blockIdx.x;
    const float* Bsrc = (g < NEXP) ? (wgu + (size_t)g * DIM * TWOF) : sgu;
    const int rowbase = (g < NEXP) ? g_off[g] : NT_TOK;

#if HAS_TCGEN05
    extern __shared__ char smraw[];
    uint32_t sb = (smem_u32(smraw) + 1023u) & ~1023u;
    // hdr: FULL[3] @0,8,16 ; DONE[3] @24,32,40 ; TP @48
    const uint32_t TP  = sb + 48;
    const uint32_t BUF = sb + 1024;

    const int tid = threadIdx.x, wid = tid >> 5, lane = tid & 31;

    if (wid == 0) { TC_ALLOC(TP, 512); TC_RELINQ(); }
    if (tid == 0) {
#pragma unroll
        for (int s = 0; s < 3; s++) { MBAR_INIT(sb + s * 8, 512); MBAR_INIT(sb + 24 + s * 8, 1); }
    }
    __syncthreads();
    uint32_t tb;
    asm volatile("ld.shared.b32 %0, [%1];" : "=r"(tb) : "r"(TP));

    const int T = DIM / 32;

    if (tid < 512) {
        // ================= producer warps =================
        const int ar  = tid >> 3;          // 64 row groups
        const int akc = (tid & 7) * 4;     // k offset (floats)
        const float* abase = g_X + (size_t)(rowbase + m0) * DIM + akc;
        uint32_t aoff[4];
#pragma unroll
        for (int j = 0; j < 4; j++)
            aoff[j] = SW128((uint32_t)((ar + 64 * j) * 128 + akc * 4));

        const int bn  = wid * 16 + (lane & 15);   // n in [0,256)
        const int bk0 = (lane >> 4) * 4;          // k subgroup 0 or 4
        const int gcol = (bn < 128) ? (hb * 128 + bn) : (FDIM + hb * 128 + bn - 128);
        const float* bptr = Bsrc + (size_t)bk0 * TWOF + gcol;
        uint32_t boff[4];
#pragma unroll
        for (int i = 0; i < 4; i++)
            boff[i] = SW128((uint32_t)(bn * 128 + (bk0 + 8 * i) * 4));

        float4 rA[4]; float rB[4][4];
#pragma unroll
        for (int j = 0; j < 4; j++) rA[j] = *(const float4*)(abase + (size_t)(ar + 64 * j) * DIM);
#pragma unroll
        for (int i = 0; i < 4; i++)
#pragma unroll
            for (int d = 0; d < 4; d++) rB[i][d] = bptr[(size_t)(8 * i + d) * TWOF];

        int phD[3] = {0, 0, 0};
        for (int t = 0; t < T; t++) {
            const int s = t % 3;
            const uint32_t Ab = BUF + (uint32_t)s * STAGE_BYTES;
            const uint32_t Bb = Ab + 32768;
            if (t >= 3) { MBAR_WAIT(sb + 24 + s * 8, phD[s]); phD[s] ^= 1; }
#pragma unroll
            for (int j = 0; j < 4; j++)
                STS128(Ab + aoff[j], __float_as_uint(rA[j].x), __float_as_uint(rA[j].y),
                                     __float_as_uint(rA[j].z), __float_as_uint(rA[j].w));
#pragma unroll
            for (int i = 0; i < 4; i++)
                STS128(Bb + boff[i], tf32u(rB[i][0]), tf32u(rB[i][1]),
                                     tf32u(rB[i][2]), tf32u(rB[i][3]));
            FENCE_ASYNC();
            MBAR_ARRIVE(sb + s * 8);
            if (t + 1 < T) {
                const float* asrc = abase + (t + 1) * 32;
#pragma unroll
                for (int j = 0; j < 4; j++) rA[j] = *(const float4*)(asrc + (size_t)(ar + 64 * j) * DIM);
                const float* bsrc = bptr + (size_t)(t + 1) * 32 * TWOF;
#pragma unroll
                for (int i = 0; i < 4; i++)
#pragma unroll
                    for (int d = 0; d < 4; d++) rB[i][d] = bsrc[(size_t)(8 * i + d) * TWOF];
            }
        }
        { const int sf = (T - 1) % 3; MBAR_WAIT(sb + 24 + sf * 8, phD[sf]); }
    } else {
        // ================= MMA warp (warp 16) =================
        if (elect_one()) {
            int phF[3] = {0, 0, 0};
            for (int t = 0; t < T; t++) {
                const int s = t % 3;
                const uint32_t Ab = BUF + (uint32_t)s * STAGE_BYTES;
                const uint32_t Bb = Ab + 32768;
                MBAR_WAIT(sb + s * 8, phF[s]); phF[s] ^= 1;
                uint64_t dA0 = make_desc_sw128(Ab);
                uint64_t dA1 = make_desc_sw128(Ab + 16384);
                uint64_t dB  = make_desc_sw128(Bb);
#pragma unroll
                for (int c = 0; c < 4; c++) {
                    uint32_t en = (t > 0 || c > 0) ? 1u : 0u;
                    mma_tf32_ss(tb,       dA0 + c * 2, dB + c * 2, IDESC_TF32_M128_N256, en);
                    mma_tf32_ss(tb + 256, dA1 + c * 2, dB + c * 2, IDESC_TF32_M128_N256, en);
                }
                TC_COMMIT(sb + 24 + s * 8);
            }
        }
    }
    TC_FENCE_AFTER();

    // ---- epilogue (producer warps 0-15): silu(g)*u -> g_H ----
    if (wid < 16) {
        const int mh = (wid >> 2) & 1, half = wid >> 3, subp = wid & 3;
        const int row = m0 + mh * 128 + subp * 32 + lane;
        const bool ok = row < cnt;
        const size_t hbase = (size_t)(rowbase + row) * FDIM + hb * 128 + half * 64;
#pragma unroll
        for (int c = 0; c < 2; c++) {
            uint32_t gr[32], ur[32];
            uint32_t col = (uint32_t)(mh * 256 + half * 64 + c * 32);
            TC_LD_X32(gr, tb + col);
            TC_LD_X32(ur, tb + col + 128);
            TC_WAIT_LD();
            if (ok) {
                float h[32];
#pragma unroll
                for (int r = 0; r < 32; r++) {
                    float gv = __uint_as_float(gr[r]), uv = __uint_as_float(ur[r]);
                    h[r] = to_tf32(gv / (1.f + expf(-gv)) * uv);
                }
#pragma unroll
                for (int q = 0; q < 8; q++)
                    *(float4*)&g_H[hbase + c * 32 + q * 4] =
                        make_float4(h[q*4], h[q*4+1], h[q*4+2], h[q*4+3]);
            }
        }
    }
    __syncthreads();
    if (tid == 0) {
#pragma unroll
        for (int s = 0; s < 3; s++) { MBAR_INVAL(sb + s * 8); MBAR_INVAL(sb + 24 + s * 8); }
    }
    if (wid == 0) { TC_DEALLOC(tb, 512); }
#else
    // portable fallback (compute_103 pass)
    for (int idx = threadIdx.x; idx < 256 * 128; idx += NTHREADS) {
        int r = idx >> 7, cc = idx & 127;
        int row = m0 + r;
        if (row >= cnt) continue;
        const float* arow = g_X + (size_t)(rowbase + row) * DIM;
        int col = hb * 128 + cc;
        float sg = 0.f, su = 0.f;
        for (int k = 0; k < DIM; k++) {
            float a = arow[k];
            sg += a * to_tf32(Bsrc[(size_t)k * TWOF + col]);
            su += a * to_tf32(Bsrc[(size_t)k * TWOF + FDIM + col]);
        }
        g_H[(size_t)(rowbase + row) * FDIM + col] = to_tf32(sg / (1.f + expf(-sg)) * su);
    }
#endif
}

// ================= GEMM2: out (+)= H @ Wdn =================
// M=256 slots x N=256 cols. grid: (DIM/256, NT_TOK/256, nz), block 544.
__global__ __launch_bounds__(NTHREADS, 1) void gemm2_tc(
    const float* __restrict__ wdn,
    const float* __restrict__ sdn,
    float* __restrict__ out,
    int gstart, int accumulate)
{
    const int g   = gstart + blockIdx.z;
    const int cnt = (g < NEXP) ? g_cnt[g] : NT_TOK;
    const int m0  = blockIdx.y * 256;
    if (m0 >= cnt) return;
    const int n0  = blockIdx.x * 256;
    const float* Bsrc = (g < NEXP) ? (wdn + (size_t)g * FDIM * DIM) : sdn;
    const int rowbase = (g < NEXP) ? g_off[g] : NT_TOK;

#if HAS_TCGEN05
    extern __shared__ char smraw[];
    uint32_t sb = (smem_u32(smraw) + 1023u) & ~1023u;
    const uint32_t TP  = sb + 48;
    const uint32_t BUF = sb + 1024;

    const int tid = threadIdx.x, wid = tid >> 5, lane = tid & 31;

    if (wid == 0) { TC_ALLOC(TP, 512); TC_RELINQ(); }
    if (tid == 0) {
#pragma unroll
        for (int s = 0; s < 3; s++) { MBAR_INIT(sb + s * 8, 512); MBAR_INIT(sb + 24 + s * 8, 1); }
    }
    __syncthreads();
    uint32_t tb;
    asm volatile("ld.shared.b32 %0, [%1];" : "=r"(tb) : "r"(TP));

    const int T = FDIM / 32;

    if (tid < 512) {
        const int ar  = tid >> 3;
        const int akc = (tid & 7) * 4;
        const float* abase = g_H + (size_t)(rowbase + m0) * FDIM + akc;
        uint32_t aoff[4];
#pragma unroll
        for (int j = 0; j < 4; j++)
            aoff[j] = SW128((uint32_t)((ar + 64 * j) * 128 + akc * 4));

        const int bn  = wid * 16 + (lane & 15);
        const int bk0 = (lane >> 4) * 4;
        const float* bptr = Bsrc + (size_t)bk0 * DIM + n0 + bn;
        uint32_t boff[4];
#pragma unroll
        for (int i = 0; i < 4; i++)
            boff[i] = SW128((uint32_t)(bn * 128 + (bk0 + 8 * i) * 4));

        float4 rA[4]; float rB[4][4];
#pragma unroll
        for (int j = 0; j < 4; j++) rA[j] = *(const float4*)(abase + (size_t)(ar + 64 * j) * FDIM);
#pragma unroll
        for (int i = 0; i < 4; i++)
#pragma unroll
            for (int d = 0; d < 4; d++) rB[i][d] = bptr[(size_t)(8 * i + d) * DIM];

        int phD[3] = {0, 0, 0};
        for (int t = 0; t < T; t++) {
            const int s = t % 3;
            const uint32_t Ab = BUF + (uint32_t)s * STAGE_BYTES;
            const uint32_t Bb = Ab + 32768;
            if (t >= 3) { MBAR_WAIT(sb + 24 + s * 8, phD[s]); phD[s] ^= 1; }
#pragma unroll
            for (int j = 0; j < 4; j++)
                STS128(Ab + aoff[j], __float_as_uint(rA[j].x), __float_as_uint(rA[j].y),
                                     __float_as_uint(rA[j].z), __float_as_uint(rA[j].w));
#pragma unroll
            for (int i = 0; i < 4; i++)
                STS128(Bb + boff[i], tf32u(rB[i][0]), tf32u(rB[i][1]),
                                     tf32u(rB[i][2]), tf32u(rB[i][3]));
            FENCE_ASYNC();
            MBAR_ARRIVE(sb + s * 8);
            if (t + 1 < T) {
                const float* asrc = abase + (t + 1) * 32;
#pragma unroll
                for (int j = 0; j < 4; j++) rA[j] = *(const float4*)(asrc + (size_t)(ar + 64 * j) * FDIM);
                const float* bsrc = bptr + (size_t)(t + 1) * 32 * DIM;
#pragma unroll
                for (int i = 0; i < 4; i++)
#pragma unroll
                    for (int d = 0; d < 4; d++) rB[i][d] = bsrc[(size_t)(8 * i + d) * DIM];
            }
        }
        { const int sf = (T - 1) % 3; MBAR_WAIT(sb + 24 + sf * 8, phD[sf]); }
    } else {
        if (elect_one()) {
            int phF[3] = {0, 0, 0};
            for (int t = 0; t < T; t++) {
                const int s = t % 3;
                const uint32_t Ab = BUF + (uint32_t)s * STAGE_BYTES;
                const uint32_t Bb = Ab + 32768;
                MBAR_WAIT(sb + s * 8, phF[s]); phF[s] ^= 1;
                uint64_t dA0 = make_desc_sw128(Ab);
                uint64_t dA1 = make_desc_sw128(Ab + 16384);
                uint64_t dB  = make_desc_sw128(Bb);
#pragma unroll
                for (int c = 0; c < 4; c++) {
                    uint32_t en = (t > 0 || c > 0) ? 1u : 0u;
                    mma_tf32_ss(tb,       dA0 + c * 2, dB + c * 2, IDESC_TF32_M128_N256, en);
                    mma_tf32_ss(tb + 256, dA1 + c * 2, dB + c * 2, IDESC_TF32_M128_N256, en);
                }
                TC_COMMIT(sb + 24 + s * 8);
            }
        }
    }
    TC_FENCE_AFTER();

    // ---- epilogue (warps 0-15): scatter (routed: store; shared: add) ----
    if (wid < 16) {
        const int mh = (wid >> 2) & 1, half = wid >> 3, subp = wid & 3;
        const int row = m0 + mh * 128 + subp * 32 + lane;
        const bool ok = row < cnt;
        int tok = 0;
        if (ok) tok = (g < NEXP) ? g_list[g * NT_TOK + row] : row;
        const size_t obase = (size_t)tok * DIM + n0 + half * 128;
#pragma unroll
        for (int c = 0; c < 4; c++) {
            uint32_t dr[32];
            uint32_t col = (uint32_t)(mh * 256 + half * 128 + c * 32);
            TC_LD_X32(dr, tb + col);
            TC_WAIT_LD();
            if (ok) {
                if (accumulate) {
#pragma unroll
                    for (int q = 0; q < 8; q++) {
                        float4 o = *(float4*)&out[obase + c * 32 + q * 4];
                        o.x += __uint_as_float(dr[q*4]);   o.y += __uint_as_float(dr[q*4+1]);
                        o.z += __uint_as_float(dr[q*4+2]); o.w += __uint_as_float(dr[q*4+3]);
                        *(float4*)&out[obase + c * 32 + q * 4] = o;
                    }
                } else {
#pragma unroll
                    for (int q = 0; q < 8; q++)
                        *(float4*)&out[obase + c * 32 + q * 4] =
                            make_float4(__uint_as_float(dr[q*4]),   __uint_as_float(dr[q*4+1]),
                                        __uint_as_float(dr[q*4+2]), __uint_as_float(dr[q*4+3]));
                }
            }
        }
    }
    __syncthreads();
    if (tid == 0) {
#pragma unroll
        for (int s = 0; s < 3; s++) { MBAR_INVAL(sb + s * 8); MBAR_INVAL(sb + 24 + s * 8); }
    }
    if (wid == 0) { TC_DEALLOC(tb, 512); }
#else
    // portable fallback (compute_103 pass)
    for (int idx = threadIdx.x; idx < 256 * 256; idx += NTHREADS) {
        int r = idx >> 8, cc = idx & 255;
        int row = m0 + r;
        if (row >= cnt) continue;
        const float* arow = g_H + (size_t)(rowbase + row) * FDIM;
        int col = n0 + cc;
        float s = 0.f;
        for (int k = 0; k < FDIM; k++)
            s += arow[k] * to_tf32(Bsrc[(size_t)k * DIM + col]);
        int tok = (g < NEXP) ? g_list[g * NT_TOK + row] : row;
        size_t o = (size_t)tok * DIM + col;
        if (accumulate) out[o] += s; else out[o] = s;
    }
#endif
}

// ---------------- launch ----------------
extern "C" void kernel_launch(void* const* d_in, const int* in_sizes, int n_in,
                              void* d_out, int out_size)
{
    const float* x   = (const float*)d_in[0];
    const float* rw  = (const float*)d_in[1];
    const float* wgu = (const float*)d_in[2];
    const float* wdn = (const float*)d_in[3];
    const float* sgu = (const float*)d_in[4];
    const float* sdn = (const float*)d_in[5];
    float* out = (float*)d_out;

    cudaFuncSetAttribute(gemm1_tc, cudaFuncAttributeMaxDynamicSharedMemorySize, SMEM_BYTES);
    cudaFuncSetAttribute(gemm2_tc, cudaFuncAttributeMaxDynamicSharedMemorySize, SMEM_BYTES);

    zero_kernel<<<1, 32>>>();
    router_kernel<<<NT_TOK / 8, 256>>>(x, rw);
    finalize_kernel<<<1, 1>>>();
    gather_kernel<<<2 * NT_TOK, 256>>>(x);
    gemm1_tc<<<dim3(FDIM / 128, NT_TOK / 256, 9), NTHREADS, SMEM_BYTES>>>(wgu, sgu);
    gemm2_tc<<<dim3(DIM / 256, NT_TOK / 256, NEXP), NTHREADS, SMEM_BYTES>>>(wdn, sdn, out, 0, 0);
    gemm2_tc<<<dim3(DIM / 256, NT_TOK / 256, 1), NTHREADS, SMEM_BYTES>>>(wdn, sdn, out, 8, 1);
}

// round 12
// speedup vs baseline: 3.4921x; 1.0257x over previous
#include <cuda_runtime.h>
#include <cstdint>

#define NT_TOK 4096
#define DIM    2048
#define FDIM   4096
#define TWOF   8192
#define NEXP   8

// ---------------- static device scratch ----------------
__device__ int   g_cnt[9];
__device__ int   g_off[9];
__device__ int   g_list[NEXP * NT_TOK];
__device__ float g_gate[NEXP * NT_TOK];
__device__ float g_X[2 * NT_TOK * (size_t)DIM];   // gathered gated input (tf32)
__device__ float g_H[2 * NT_TOK * (size_t)FDIM];  // silu(g)*u (tf32)

// ---------------- helpers (arch-neutral) ----------------
__device__ __forceinline__ float to_tf32(float x) {
    uint32_t u; asm("cvt.rna.tf32.f32 %0, %1;" : "=r"(u) : "f"(x));
    return __uint_as_float(u);
}
__device__ __forceinline__ uint32_t tf32u(float x) {
    uint32_t u; asm("cvt.rna.tf32.f32 %0, %1;" : "=r"(u) : "f"(x));
    return u;
}
__device__ __forceinline__ uint32_t smem_u32(const void* p) {
    uint32_t a;
    asm("{ .reg .u64 t; cvta.to.shared.u64 t, %1; cvt.u32.u64 %0, t; }" : "=r"(a) : "l"(p));
    return a;
}
#define SW128(o) ((o) ^ (((o) >> 3) & 0x70))

#if defined(__CUDA_ARCH__) && defined(__CUDA_ARCH_FEAT_SM103_ALL)
#define HAS_TCGEN05 1
#else
#define HAS_TCGEN05 0
#endif

#if HAS_TCGEN05
__device__ __forceinline__ uint32_t elect_one() {
    uint32_t p;
    asm volatile("{\n\t.reg .pred p;\n\telect.sync _|p, 0xFFFFFFFF;\n\t"
                 "selp.b32 %0, 1, 0, p;\n\t}" : "=r"(p));
    return p;
}
static __device__ __forceinline__ uint64_t make_desc_sw128(uint32_t addr) {
    const uint64_t base =
        (uint64_t(2) << 61) | (uint64_t(1) << 46) | (uint64_t(64) << 32) | (uint64_t(1) << 16);
    return base | ((uint64_t)(addr >> 4) & 0x3FFF);
}
// cg2 tf32: dtype=F32(1)<<4 | atype=TF32(2)<<7 | btype=TF32(2)<<10 | (N/8)<<17 | (M/16)<<24
#define IDESC_CG2 ((1u<<4)|(2u<<7)|(2u<<10)|((256u/8)<<17)|((256u/16)<<24))

__device__ __forceinline__ void mma_tf32_ss_cg2(uint32_t d, uint64_t da, uint64_t db,
                                                uint32_t idesc, uint32_t en) {
    asm volatile(
        "{\n\t.reg .pred p;\n\tsetp.ne.u32 p, %4, 0;\n\t"
        "tcgen05.mma.cta_group::2.kind::tf32 [%0], %1, %2, %3, "
        "{%5, %5, %5, %5, %5, %5, %5, %5}, p;\n\t}"
        :: "r"(d), "l"(da), "l"(db), "r"(idesc), "r"(en), "r"(0u) : "memory");
}

#define TC_ALLOC_CG2(sm, n)   asm volatile("tcgen05.alloc.cta_group::2.sync.aligned.shared::cta.b32 [%0], %1;" :: "r"(sm), "r"(n) : "memory")
#define TC_DEALLOC_CG2(tb, n) asm volatile("tcgen05.dealloc.cta_group::2.sync.aligned.b32 %0, %1;" :: "r"(tb), "r"(n))
#define TC_RELINQ_CG2()       asm volatile("tcgen05.relinquish_alloc_permit.cta_group::2.sync.aligned;")
#define TC_COMMIT_MC_CG2(mb, mask) \
    asm volatile("tcgen05.commit.cta_group::2.mbarrier::arrive::one.shared::cluster.multicast::cluster.b64 [%0], %1;" \
                 :: "r"(mb), "h"((uint16_t)(mask)) : "memory")
#define TC_FENCE_AFTER()  asm volatile("tcgen05.fence::after_thread_sync;" ::: "memory")
#define TC_WAIT_LD()      asm volatile("tcgen05.wait::ld.sync.aligned;" ::: "memory")
#define FENCE_ASYNC()     asm volatile("fence.proxy.async.shared::cta;" ::: "memory")
#define MBAR_INIT(mb, c)  asm volatile("mbarrier.init.shared.b64 [%0], %1;" :: "r"(mb), "r"(c) : "memory")
#define MBAR_INVAL(mb)    asm volatile("mbarrier.inval.shared.b64 [%0];" :: "r"(mb) : "memory")
// arrive on the LEADER CTA's mbarrier (clear peer bit 24)
#define MBAR_ARRIVE_LEADER(mb)                                                       \
    asm volatile("{\n\t.reg .b32 la;\n\tand.b32 la, %0, 0xFEFFFFFF;\n\t"             \
                 "mbarrier.arrive.shared::cluster.b64 _, [la];\n\t}"                 \
                 :: "r"(mb) : "memory")
#define CLUSTER_SYNC() do {                                                          \
    asm volatile("barrier.cluster.arrive.aligned;" ::: "memory");                    \
    asm volatile("barrier.cluster.wait.aligned;" ::: "memory");                      \
} while (0)

#define MBAR_WAIT(mb, ph) do {                                                       \
    uint32_t _m = (mb); uint32_t _p = (ph); uint32_t _d;                             \
    asm volatile("{\n\t.reg .pred p;\n\t"                                            \
        "mbarrier.try_wait.parity.acquire.cta.shared::cta.b64 p, [%1], %2;\n\t"      \
        "selp.b32 %0, 1, 0, p;\n\t}" : "=r"(_d) : "r"(_m), "r"(_p) : "memory");      \
    if (!_d) {                                                                       \
        asm volatile("{\n\t.reg .pred P1;\n\tWL_%=:\n\t"                             \
            "mbarrier.try_wait.parity.acquire.cta.shared::cta.b64 P1, [%0], %1, 0x989680;\n\t" \
            "@P1 bra.uni WD_%=;\n\tbra.uni WL_%=;\n\tWD_%=:\n\t}"                    \
            :: "r"(_m), "r"(_p) : "memory");                                         \
    }                                                                                \
} while (0)

#define TC_LD_X32(r, addr)                                                           \
    asm volatile("tcgen05.ld.sync.aligned.32x32b.x32.b32 "                           \
        "{%0,%1,%2,%3,%4,%5,%6,%7,%8,%9,%10,%11,%12,%13,%14,%15,"                    \
        "%16,%17,%18,%19,%20,%21,%22,%23,%24,%25,%26,%27,%28,%29,%30,%31}, [%32];"   \
        : "=r"((r)[0]),"=r"((r)[1]),"=r"((r)[2]),"=r"((r)[3]),                       \
          "=r"((r)[4]),"=r"((r)[5]),"=r"((r)[6]),"=r"((r)[7]),                       \
          "=r"((r)[8]),"=r"((r)[9]),"=r"((r)[10]),"=r"((r)[11]),                     \
          "=r"((r)[12]),"=r"((r)[13]),"=r"((r)[14]),"=r"((r)[15]),                   \
          "=r"((r)[16]),"=r"((r)[17]),"=r"((r)[18]),"=r"((r)[19]),                   \
          "=r"((r)[20]),"=r"((r)[21]),"=r"((r)[22]),"=r"((r)[23]),                   \
          "=r"((r)[24]),"=r"((r)[25]),"=r"((r)[26]),"=r"((r)[27]),                   \
          "=r"((r)[28]),"=r"((r)[29]),"=r"((r)[30]),"=r"((r)[31])                    \
        : "r"(addr))

#define STS128(addr, a, b, c, d)                                                     \
    asm volatile("st.shared.v4.b32 [%0], {%1, %2, %3, %4};"                          \
                 :: "r"(addr), "r"(a), "r"(b), "r"(c), "r"(d) : "memory")
#endif  // HAS_TCGEN05

// 4-stage ring: stage = A(16KB) + B(32KB) = 48KB per CTA
#define STAGE_BYTES 49152
#define NSTAGE 4
#define SMEM_BYTES (2048 + NSTAGE * STAGE_BYTES)
#define NTHREADS 544

// ---------------- router ----------------
__global__ void zero_kernel() { if (threadIdx.x < 9) g_cnt[threadIdx.x] = 0; }

__global__ __launch_bounds__(256) void router_kernel(
    const float* __restrict__ x, const float* __restrict__ rw)
{
    int t = blockIdx.x * 8 + (threadIdx.x >> 5);
    int lane = threadIdx.x & 31;
    const float* xr = x + (size_t)t * DIM;
    float p[8];
#pragma unroll
    for (int e = 0; e < 8; e++) p[e] = 0.f;
    for (int k = lane; k < DIM; k += 32) {
        float xv = xr[k];
#pragma unroll
        for (int e = 0; e < 8; e++) p[e] += xv * rw[e * DIM + k];
    }
#pragma unroll
    for (int e = 0; e < 8; e++)
#pragma unroll
        for (int o = 16; o > 0; o >>= 1) p[e] += __shfl_xor_sync(~0u, p[e], o);
    if (lane == 0) {
        float best = p[0]; int bi = 0;
#pragma unroll
        for (int e = 1; e < 8; e++) if (p[e] > best) { best = p[e]; bi = e; }
        float gate = 1.0f / (1.0f + expf(-best));
        int pos = atomicAdd(&g_cnt[bi], 1);
        g_list[bi * NT_TOK + pos] = t;
        g_gate[bi * NT_TOK + pos] = gate;
    }
}

__global__ void finalize_kernel() {
    int o = 0;
    for (int e = 0; e < 8; e++) { g_off[e] = o; o += g_cnt[e]; }
    g_off[8] = NT_TOK;
}

// ---------------- gather: g_X[slot] = tf32(gate * x[tok]) ----------------
__global__ __launch_bounds__(256) void gather_kernel(const float* __restrict__ x)
{
    int row = blockIdx.x;
    int tok; float gate;
    if (row < NT_TOK) {
        int e = 0;
#pragma unroll
        for (int i = 1; i < 8; i++) if (row >= g_off[i]) e = i;
        int idx = row - g_off[e];
        tok  = g_list[e * NT_TOK + idx];
        gate = g_gate[e * NT_TOK + idx];
    } else { tok = row - NT_TOK; gate = 1.f; }
    const float4* src = (const float4*)(x + (size_t)tok * DIM);
    float4* dst = (float4*)(g_X + (size_t)row * DIM);
    for (int j = threadIdx.x; j < DIM / 4; j += 256) {
        float4 v = src[j];
        v.x = to_tf32(v.x * gate); v.y = to_tf32(v.y * gate);
        v.z = to_tf32(v.z * gate); v.w = to_tf32(v.w * gate);
        dst[j] = v;
    }
}

// ================= GEMM1 (cg2 pair tile M=256 x N=512 = gate256|up256) =======
// grid: (2*FDIM/256, NT_TOK/256, 9), cluster (2,1,1), block 544.
__global__ __launch_bounds__(NTHREADS, 1) __cluster_dims__(2, 1, 1)
void gemm1_tc(const float* __restrict__ wgu, const float* __restrict__ sgu)
{
    const int g   = blockIdx.z;
    const int cnt = (g < NEXP) ? g_cnt[g] : NT_TOK;
    const int m0  = blockIdx.y * 256;
    if (m0 >= cnt) return;                   // uniform across the pair
    const int hb  = blockIdx.x >> 1;         // 16 h-blocks of 256 cols
    const int rank = blockIdx.x & 1;
    const float* Bsrc = (g < NEXP) ? (wgu + (size_t)g * DIM * TWOF) : sgu;
    const int rowbase = (g < NEXP) ? g_off[g] : NT_TOK;

#if HAS_TCGEN05
    extern __shared__ char smraw[];
    uint32_t sb = (smem_u32(smraw) + 1023u) & ~1023u;
    // hdr: full[4]@0..24 ; done[4]@32..56 ; TP@64
    const uint32_t TP  = sb + 64;
    const uint32_t BUF = sb + 1024;

    const int tid = threadIdx.x, wid = tid >> 5, lane = tid & 31;

    if (wid == 0) { TC_ALLOC_CG2(TP, 512); TC_RELINQ_CG2(); }
    if (tid == 0) {
#pragma unroll
        for (int s = 0; s < 4; s++) { MBAR_INIT(sb + s * 8, 1024); MBAR_INIT(sb + 32 + s * 8, 1); }
    }
    __syncthreads();
    CLUSTER_SYNC();   // mbar init visible before cross-CTA arrivals / peer smem reads
    uint32_t tb;
    asm volatile("ld.shared.b32 %0, [%1];" : "=r"(tb) : "r"(TP));

    const int T = DIM / 32;

    if (tid < 512) {
        // ---- producers: A = 128 rows (this rank's half), B = 256 cols (rank halves per atom)
        const int ar  = tid >> 3;            // 0..63 (+64 for second chunk)
        const int akc = (tid & 7) * 4;       // k float offset
        const float* abase = g_X + (size_t)(rowbase + m0 + rank * 128) * DIM + akc;
        uint32_t aoff[2];
#pragma unroll
        for (int j = 0; j < 2; j++)
            aoff[j] = SW128((uint32_t)((ar + 64 * j) * 128 + akc * 4));

        const int bn  = wid * 16 + (lane & 15);   // smem B row 0..255
        const int bk0 = (lane >> 4) * 4;
        const int atom = bn >> 7, within = bn & 127;
        const int gcol = (atom == 0)
            ? (hb * 256 + rank * 128 + within)                 // gate cols
            : (FDIM + hb * 256 + rank * 128 + within);         // up cols
        const float* bptr = Bsrc + (size_t)bk0 * TWOF + gcol;
        uint32_t boff[4];
#pragma unroll
        for (int i = 0; i < 4; i++)
            boff[i] = SW128((uint32_t)(bn * 128 + (bk0 + 8 * i) * 4));

        float4 rA[2]; float rB[4][4];
#pragma unroll
        for (int j = 0; j < 2; j++) rA[j] = *(const float4*)(abase + (size_t)(ar + 64 * j) * DIM);
#pragma unroll
        for (int i = 0; i < 4; i++)
#pragma unroll
            for (int d = 0; d < 4; d++) rB[i][d] = bptr[(size_t)(8 * i + d) * TWOF];

        int phD[4] = {0, 0, 0, 0};
        for (int t = 0; t < T; t++) {
            const int s = t & 3;
            const uint32_t Ab = BUF + (uint32_t)s * STAGE_BYTES;
            const uint32_t Bb = Ab + 16384;
            if (t >= 4) { MBAR_WAIT(sb + 32 + s * 8, phD[s]); phD[s] ^= 1; }
#pragma unroll
            for (int j = 0; j < 2; j++)
                STS128(Ab + aoff[j], __float_as_uint(rA[j].x), __float_as_uint(rA[j].y),
                                     __float_as_uint(rA[j].z), __float_as_uint(rA[j].w));
#pragma unroll
            for (int i = 0; i < 4; i++)
                STS128(Bb + boff[i], tf32u(rB[i][0]), tf32u(rB[i][1]),
                                     tf32u(rB[i][2]), tf32u(rB[i][3]));
            FENCE_ASYNC();
            MBAR_ARRIVE_LEADER(sb + s * 8);
            if (t + 1 < T) {
                const float* asrc = abase + (t + 1) * 32;
#pragma unroll
                for (int j = 0; j < 2; j++) rA[j] = *(const float4*)(asrc + (size_t)(ar + 64 * j) * DIM);
                const float* bsrc = bptr + (size_t)(t + 1) * 32 * TWOF;
#pragma unroll
                for (int i = 0; i < 4; i++)
#pragma unroll
                    for (int d = 0; d < 4; d++) rB[i][d] = bsrc[(size_t)(8 * i + d) * TWOF];
            }
        }
        { const int sf = (T - 1) & 3; MBAR_WAIT(sb + 32 + sf * 8, phD[sf]); }
    } else if (rank == 0) {
        // ---- MMA warp: leader only
        if (elect_one()) {
            int phF[4] = {0, 0, 0, 0};
            for (int t = 0; t < T; t++) {
                const int s = t & 3;
                const uint32_t Ab = BUF + (uint32_t)s * STAGE_BYTES;
                const uint32_t Bb = Ab + 16384;
                MBAR_WAIT(sb + s * 8, phF[s]); phF[s] ^= 1;
                uint64_t dA = make_desc_sw128(Ab);
                uint64_t dB = make_desc_sw128(Bb);
#pragma unroll
                for (int c = 0; c < 4; c++) {
                    uint32_t en = (t > 0 || c > 0) ? 1u : 0u;
                    mma_tf32_ss_cg2(tb,       dA + c * 2, dB + c * 2,        IDESC_CG2, en);
                    mma_tf32_ss_cg2(tb + 256, dA + c * 2, dB + 1024 + c * 2, IDESC_CG2, en);
                }
                TC_COMMIT_MC_CG2(sb + 32 + s * 8, 0x3);
            }
        }
    }
    TC_FENCE_AFTER();

    // ---- epilogue: my 128 rows x 512 cols (gate atom0 | up atom1) -> g_H ----
    if (wid < 16) {
        const int rloc = (wid & 3) * 32 + lane;
        const int row  = m0 + rank * 128 + rloc;
        const bool ok  = row < cnt;
        const int cq   = wid >> 2;   // 0..3, 64 gate cols each
        const size_t hbase = (size_t)(rowbase + row) * FDIM + hb * 256 + cq * 64;
#pragma unroll
        for (int c = 0; c < 2; c++) {
            uint32_t gr[32], ur[32];
            uint32_t col = (uint32_t)(cq * 64 + c * 32);
            TC_LD_X32(gr, tb + col);
            TC_LD_X32(ur, tb + 256 + col);
            TC_WAIT_LD();
            if (ok) {
                float h[32];
#pragma unroll
                for (int r = 0; r < 32; r++) {
                    float gv = __uint_as_float(gr[r]), uv = __uint_as_float(ur[r]);
                    h[r] = to_tf32(gv / (1.f + expf(-gv)) * uv);
                }
#pragma unroll
                for (int q = 0; q < 8; q++)
                    *(float4*)&g_H[hbase + c * 32 + q * 4] =
                        make_float4(h[q*4], h[q*4+1], h[q*4+2], h[q*4+3]);
            }
        }
    }
    __syncthreads();
    if (tid == 0) {
#pragma unroll
        for (int s = 0; s < 4; s++) { MBAR_INVAL(sb + s * 8); MBAR_INVAL(sb + 32 + s * 8); }
    }
    __syncthreads();
    if (wid == 0) { TC_DEALLOC_CG2(tb, 512); }
    CLUSTER_SYNC();
#else
    // portable fallback
    for (int idx = threadIdx.x; idx < 128 * 256; idx += NTHREADS) {
        int r = idx >> 8, cc = idx & 255;
        int row = m0 + rank * 128 + r;
        if (row >= cnt) continue;
        const float* arow = g_X + (size_t)(rowbase + row) * DIM;
        int col = hb * 256 + cc;
        float sg = 0.f, su = 0.f;
        for (int k = 0; k < DIM; k++) {
            float a = arow[k];
            sg += a * to_tf32(Bsrc[(size_t)k * TWOF + col]);
            su += a * to_tf32(Bsrc[(size_t)k * TWOF + FDIM + col]);
        }
        g_H[(size_t)(rowbase + row) * FDIM + col] = to_tf32(sg / (1.f + expf(-sg)) * su);
    }
#endif
}

// ================= GEMM2 (cg2 pair tile M=256 x N=512) =================
// grid: (2*DIM/512, NT_TOK/256, nz), cluster (2,1,1), block 544.
__global__ __launch_bounds__(NTHREADS, 1) __cluster_dims__(2, 1, 1)
void gemm2_tc(const float* __restrict__ wdn, const float* __restrict__ sdn,
              float* __restrict__ out, int gstart, int accumulate)
{
    const int g   = gstart + blockIdx.z;
    const int cnt = (g < NEXP) ? g_cnt[g] : NT_TOK;
    const int m0  = blockIdx.y * 256;
    if (m0 >= cnt) return;
    const int n0  = (blockIdx.x >> 1) * 512;
    const int rank = blockIdx.x & 1;
    const float* Bsrc = (g < NEXP) ? (wdn + (size_t)g * FDIM * DIM) : sdn;
    const int rowbase = (g < NEXP) ? g_off[g] : NT_TOK;

#if HAS_TCGEN05
    extern __shared__ char smraw[];
    uint32_t sb = (smem_u32(smraw) + 1023u) & ~1023u;
    const uint32_t TP  = sb + 64;
    const uint32_t BUF = sb + 1024;

    const int tid = threadIdx.x, wid = tid >> 5, lane = tid & 31;

    if (wid == 0) { TC_ALLOC_CG2(TP, 512); TC_RELINQ_CG2(); }
    if (tid == 0) {
#pragma unroll
        for (int s = 0; s < 4; s++) { MBAR_INIT(sb + s * 8, 1024); MBAR_INIT(sb + 32 + s * 8, 1); }
    }
    __syncthreads();
    CLUSTER_SYNC();
    uint32_t tb;
    asm volatile("ld.shared.b32 %0, [%1];" : "=r"(tb) : "r"(TP));

    const int T = FDIM / 32;

    if (tid < 512) {
        const int ar  = tid >> 3;
        const int akc = (tid & 7) * 4;
        const float* abase = g_H + (size_t)(rowbase + m0 + rank * 128) * FDIM + akc;
        uint32_t aoff[2];
#pragma unroll
        for (int j = 0; j < 2; j++)
            aoff[j] = SW128((uint32_t)((ar + 64 * j) * 128 + akc * 4));

        const int bn  = wid * 16 + (lane & 15);
        const int bk0 = (lane >> 4) * 4;
        const int atom = bn >> 7, within = bn & 127;
        const int gcol = n0 + atom * 256 + rank * 128 + within;
        const float* bptr = Bsrc + (size_t)bk0 * DIM + gcol;
        uint32_t boff[4];
#pragma unroll
        for (int i = 0; i < 4; i++)
            boff[i] = SW128((uint32_t)(bn * 128 + (bk0 + 8 * i) * 4));

        float4 rA[2]; float rB[4][4];
#pragma unroll
        for (int j = 0; j < 2; j++) rA[j] = *(const float4*)(abase + (size_t)(ar + 64 * j) * FDIM);
#pragma unroll
        for (int i = 0; i < 4; i++)
#pragma unroll
            for (int d = 0; d < 4; d++) rB[i][d] = bptr[(size_t)(8 * i + d) * DIM];

        int phD[4] = {0, 0, 0, 0};
        for (int t = 0; t < T; t++) {
            const int s = t & 3;
            const uint32_t Ab = BUF + (uint32_t)s * STAGE_BYTES;
            const uint32_t Bb = Ab + 16384;
            if (t >= 4) { MBAR_WAIT(sb + 32 + s * 8, phD[s]); phD[s] ^= 1; }
#pragma unroll
            for (int j = 0; j < 2; j++)
                STS128(Ab + aoff[j], __float_as_uint(rA[j].x), __float_as_uint(rA[j].y),
                                     __float_as_uint(rA[j].z), __float_as_uint(rA[j].w));
#pragma unroll
            for (int i = 0; i < 4; i++)
                STS128(Bb + boff[i], tf32u(rB[i][0]), tf32u(rB[i][1]),
                                     tf32u(rB[i][2]), tf32u(rB[i][3]));
            FENCE_ASYNC();
            MBAR_ARRIVE_LEADER(sb + s * 8);
            if (t + 1 < T) {
                const float* asrc = abase + (t + 1) * 32;
#pragma unroll
                for (int j = 0; j < 2; j++) rA[j] = *(const float4*)(asrc + (size_t)(ar + 64 * j) * FDIM);
                const float* bsrc = bptr + (size_t)(t + 1) * 32 * DIM;
#pragma unroll
                for (int i = 0; i < 4; i++)
#pragma unroll
                    for (int d = 0; d < 4; d++) rB[i][d] = bsrc[(size_t)(8 * i + d) * DIM];
            }
        }
        { const int sf = (T - 1) & 3; MBAR_WAIT(sb + 32 + sf * 8, phD[sf]); }
    } else if (rank == 0) {
        if (elect_one()) {
            int phF[4] = {0, 0, 0, 0};
            for (int t = 0; t < T; t++) {
                const int s = t & 3;
                const uint32_t Ab = BUF + (uint32_t)s * STAGE_BYTES;
                const uint32_t Bb = Ab + 16384;
                MBAR_WAIT(sb + s * 8, phF[s]); phF[s] ^= 1;
                uint64_t dA = make_desc_sw128(Ab);
                uint64_t dB = make_desc_sw128(Bb);
#pragma unroll
                for (int c = 0; c < 4; c++) {
                    uint32_t en = (t > 0 || c > 0) ? 1u : 0u;
                    mma_tf32_ss_cg2(tb,       dA + c * 2, dB + c * 2,        IDESC_CG2, en);
                    mma_tf32_ss_cg2(tb + 256, dA + c * 2, dB + 1024 + c * 2, IDESC_CG2, en);
                }
                TC_COMMIT_MC_CG2(sb + 32 + s * 8, 0x3);
            }
        }
    }
    TC_FENCE_AFTER();

    // ---- epilogue: my 128 rows x 512 out cols ----
    if (wid < 16) {
        const int rloc = (wid & 3) * 32 + lane;
        const int row  = m0 + rank * 128 + rloc;
        const bool ok  = row < cnt;
        int tok = 0;
        if (ok) tok = (g < NEXP) ? g_list[g * NT_TOK + row] : row;
        const int cq = wid >> 2;   // 0..3, 128 cols each
        const size_t obase = (size_t)tok * DIM + n0 + cq * 128;
#pragma unroll
        for (int c = 0; c < 4; c++) {
            uint32_t dr[32];
            uint32_t col = (uint32_t)(cq * 128 + c * 32);
            TC_LD_X32(dr, tb + col);
            TC_WAIT_LD();
            if (ok) {
                if (accumulate) {
#pragma unroll
                    for (int q = 0; q < 8; q++) {
                        float4 o = *(float4*)&out[obase + c * 32 + q * 4];
                        o.x += __uint_as_float(dr[q*4]);   o.y += __uint_as_float(dr[q*4+1]);
                        o.z += __uint_as_float(dr[q*4+2]); o.w += __uint_as_float(dr[q*4+3]);
                        *(float4*)&out[obase + c * 32 + q * 4] = o;
                    }
                } else {
#pragma unroll
                    for (int q = 0; q < 8; q++)
                        *(float4*)&out[obase + c * 32 + q * 4] =
                            make_float4(__uint_as_float(dr[q*4]),   __uint_as_float(dr[q*4+1]),
                                        __uint_as_float(dr[q*4+2]), __uint_as_float(dr[q*4+3]));
                }
            }
        }
    }
    __syncthreads();
    if (tid == 0) {
#pragma unroll
        for (int s = 0; s < 4; s++) { MBAR_INVAL(sb + s * 8); MBAR_INVAL(sb + 32 + s * 8); }
    }
    __syncthreads();
    if (wid == 0) { TC_DEALLOC_CG2(tb, 512); }
    CLUSTER_SYNC();
#else
    // portable fallback
    for (int idx = threadIdx.x; idx < 128 * 512; idx += NTHREADS) {
        int r = idx >> 9, cc = idx & 511;
        int row = m0 + rank * 128 + r;
        if (row >= cnt) continue;
        const float* arow = g_H + (size_t)(rowbase + row) * FDIM;
        int col = n0 + cc;
        float s = 0.f;
        for (int k = 0; k < FDIM; k++)
            s += arow[k] * to_tf32(Bsrc[(size_t)k * DIM + col]);
        int tok = (g < NEXP) ? g_list[g * NT_TOK + row] : row;
        size_t o = (size_t)tok * DIM + col;
        if (accumulate) out[o] += s; else out[o] = s;
    }
#endif
}

// ---------------- launch ----------------
extern "C" void kernel_launch(void* const* d_in, const int* in_sizes, int n_in,
                              void* d_out, int out_size)
{
    const float* x   = (const float*)d_in[0];
    const float* rw  = (const float*)d_in[1];
    const float* wgu = (const float*)d_in[2];
    const float* wdn = (const float*)d_in[3];
    const float* sgu = (const float*)d_in[4];
    const float* sdn = (const float*)d_in[5];
    float* out = (float*)d_out;

    cudaFuncSetAttribute(gemm1_tc, cudaFuncAttributeMaxDynamicSharedMemorySize, SMEM_BYTES);
    cudaFuncSetAttribute(gemm2_tc, cudaFuncAttributeMaxDynamicSharedMemorySize, SMEM_BYTES);

    zero_kernel<<<1, 32>>>();
    router_kernel<<<NT_TOK / 8, 256>>>(x, rw);
    finalize_kernel<<<1, 1>>>();
    gather_kernel<<<2 * NT_TOK, 256>>>(x);
    gemm1_tc<<<dim3(2 * (FDIM / 256), NT_TOK / 256, 9), NTHREADS, SMEM_BYTES>>>(wgu, sgu);
    gemm2_tc<<<dim3(2 * (DIM / 512), NT_TOK / 256, NEXP), NTHREADS, SMEM_BYTES>>>(wdn, sdn, out, 0, 0);
    gemm2_tc<<<dim3(2 * (DIM / 512), NT_TOK / 256, 1), NTHREADS, SMEM_BYTES>>>(wdn, sdn, out, 8, 1);
}

// round 13
// speedup vs baseline: 3.5833x; 1.0261x over previous
#include <cuda_runtime.h>
#include <cstdint>

#define NT_TOK 4096
#define DIM    2048
#define FDIM   4096
#define TWOF   8192
#define NEXP   8

// ---------------- static device scratch ----------------
__device__ int   g_cnt[9];
__device__ int   g_off[9];
__device__ int   g_list[NEXP * NT_TOK];
__device__ float g_gate[NEXP * NT_TOK];
__device__ float g_X[2 * NT_TOK * (size_t)DIM];   // gathered gated input (tf32)
__device__ float g_H[2 * NT_TOK * (size_t)FDIM];  // silu(g)*u (tf32)

// ---------------- helpers (arch-neutral) ----------------
__device__ __forceinline__ float to_tf32(float x) {
    uint32_t u; asm("cvt.rna.tf32.f32 %0, %1;" : "=r"(u) : "f"(x));
    return __uint_as_float(u);
}
__device__ __forceinline__ uint32_t tf32u(float x) {
    uint32_t u; asm("cvt.rna.tf32.f32 %0, %1;" : "=r"(u) : "f"(x));
    return u;
}
__device__ __forceinline__ uint32_t smem_u32(const void* p) {
    uint32_t a;
    asm("{ .reg .u64 t; cvta.to.shared.u64 t, %1; cvt.u32.u64 %0, t; }" : "=r"(a) : "l"(p));
    return a;
}
#define SW128(o) ((o) ^ (((o) >> 3) & 0x70))

#if defined(__CUDA_ARCH__) && defined(__CUDA_ARCH_FEAT_SM103_ALL)
#define HAS_TCGEN05 1
#else
#define HAS_TCGEN05 0
#endif

#if HAS_TCGEN05
__device__ __forceinline__ uint32_t elect_one() {
    uint32_t p;
    asm volatile("{\n\t.reg .pred p;\n\telect.sync _|p, 0xFFFFFFFF;\n\t"
                 "selp.b32 %0, 1, 0, p;\n\t}" : "=r"(p));
    return p;
}
static __device__ __forceinline__ uint64_t make_desc_sw128(uint32_t addr) {
    const uint64_t base =
        (uint64_t(2) << 61) | (uint64_t(1) << 46) | (uint64_t(64) << 32) | (uint64_t(1) << 16);
    return base | ((uint64_t)(addr >> 4) & 0x3FFF);
}
// cg2 tf32: dtype=F32(1)<<4 | atype=TF32(2)<<7 | btype=TF32(2)<<10 | (N/8)<<17 | (M/16)<<24
#define IDESC_CG2 ((1u<<4)|(2u<<7)|(2u<<10)|((256u/8)<<17)|((256u/16)<<24))

__device__ __forceinline__ void mma_tf32_ss_cg2(uint32_t d, uint64_t da, uint64_t db,
                                                uint32_t idesc, uint32_t en) {
    asm volatile(
        "{\n\t.reg .pred p;\n\tsetp.ne.u32 p, %4, 0;\n\t"
        "tcgen05.mma.cta_group::2.kind::tf32 [%0], %1, %2, %3, "
        "{%5, %5, %5, %5, %5, %5, %5, %5}, p;\n\t}"
        :: "r"(d), "l"(da), "l"(db), "r"(idesc), "r"(en), "r"(0u) : "memory");
}

#define TC_ALLOC_CG2(sm, n)   asm volatile("tcgen05.alloc.cta_group::2.sync.aligned.shared::cta.b32 [%0], %1;" :: "r"(sm), "r"(n) : "memory")
#define TC_DEALLOC_CG2(tb, n) asm volatile("tcgen05.dealloc.cta_group::2.sync.aligned.b32 %0, %1;" :: "r"(tb), "r"(n))
#define TC_RELINQ_CG2()       asm volatile("tcgen05.relinquish_alloc_permit.cta_group::2.sync.aligned;")
#define TC_COMMIT_MC_CG2(mb, mask) \
    asm volatile("tcgen05.commit.cta_group::2.mbarrier::arrive::one.shared::cluster.multicast::cluster.b64 [%0], %1;" \
                 :: "r"(mb), "h"((uint16_t)(mask)) : "memory")
#define TC_FENCE_AFTER()  asm volatile("tcgen05.fence::after_thread_sync;" ::: "memory")
#define TC_WAIT_LD()      asm volatile("tcgen05.wait::ld.sync.aligned;" ::: "memory")
#define FENCE_ASYNC()     asm volatile("fence.proxy.async.shared::cta;" ::: "memory")
#define MBAR_INIT(mb, c)  asm volatile("mbarrier.init.shared.b64 [%0], %1;" :: "r"(mb), "r"(c) : "memory")
#define MBAR_INVAL(mb)    asm volatile("mbarrier.inval.shared.b64 [%0];" :: "r"(mb) : "memory")
// arrive on the LEADER CTA's mbarrier (clear peer bit 24)
#define MBAR_ARRIVE_LEADER(mb)                                                       \
    asm volatile("{\n\t.reg .b32 la;\n\tand.b32 la, %0, 0xFEFFFFFF;\n\t"             \
                 "mbarrier.arrive.shared::cluster.b64 _, [la];\n\t}"                 \
                 :: "r"(mb) : "memory")
#define CLUSTER_SYNC() do {                                                          \
    asm volatile("barrier.cluster.arrive.aligned;" ::: "memory");                    \
    asm volatile("barrier.cluster.wait.aligned;" ::: "memory");                      \
} while (0)

#define MBAR_WAIT(mb, ph) do {                                                       \
    uint32_t _m = (mb); uint32_t _p = (ph); uint32_t _d;                             \
    asm volatile("{\n\t.reg .pred p;\n\t"                                            \
        "mbarrier.try_wait.parity.acquire.cta.shared::cta.b64 p, [%1], %2;\n\t"      \
        "selp.b32 %0, 1, 0, p;\n\t}" : "=r"(_d) : "r"(_m), "r"(_p) : "memory");      \
    if (!_d) {                                                                       \
        asm volatile("{\n\t.reg .pred P1;\n\tWL_%=:\n\t"                             \
            "mbarrier.try_wait.parity.acquire.cta.shared::cta.b64 P1, [%0], %1, 0x989680;\n\t" \
            "@P1 bra.uni WD_%=;\n\tbra.uni WL_%=;\n\tWD_%=:\n\t}"                    \
            :: "r"(_m), "r"(_p) : "memory");                                         \
    }                                                                                \
} while (0)

#define TC_LD_X32(r, addr)                                                           \
    asm volatile("tcgen05.ld.sync.aligned.32x32b.x32.b32 "                           \
        "{%0,%1,%2,%3,%4,%5,%6,%7,%8,%9,%10,%11,%12,%13,%14,%15,"                    \
        "%16,%17,%18,%19,%20,%21,%22,%23,%24,%25,%26,%27,%28,%29,%30,%31}, [%32];"   \
        : "=r"((r)[0]),"=r"((r)[1]),"=r"((r)[2]),"=r"((r)[3]),                       \
          "=r"((r)[4]),"=r"((r)[5]),"=r"((r)[6]),"=r"((r)[7]),                       \
          "=r"((r)[8]),"=r"((r)[9]),"=r"((r)[10]),"=r"((r)[11]),                     \
          "=r"((r)[12]),"=r"((r)[13]),"=r"((r)[14]),"=r"((r)[15]),                   \
          "=r"((r)[16]),"=r"((r)[17]),"=r"((r)[18]),"=r"((r)[19]),                   \
          "=r"((r)[20]),"=r"((r)[21]),"=r"((r)[22]),"=r"((r)[23]),                   \
          "=r"((r)[24]),"=r"((r)[25]),"=r"((r)[26]),"=r"((r)[27]),                   \
          "=r"((r)[28]),"=r"((r)[29]),"=r"((r)[30]),"=r"((r)[31])                    \
        : "r"(addr))

#define STS128(addr, a, b, c, d)                                                     \
    asm volatile("st.shared.v4.b32 [%0], {%1, %2, %3, %4};"                          \
                 :: "r"(addr), "r"(a), "r"(b), "r"(c), "r"(d) : "memory")
#endif  // HAS_TCGEN05

// 4-stage ring: stage = A(16KB) + B(32KB) = 48KB per CTA
#define STAGE_BYTES 49152
#define NSTAGE 4
#define SMEM_BYTES (2048 + NSTAGE * STAGE_BYTES)
#define NTHREADS 544

// ---------------- router ----------------
__global__ void zero_kernel() { if (threadIdx.x < 9) g_cnt[threadIdx.x] = 0; }

__global__ __launch_bounds__(256) void router_kernel(
    const float* __restrict__ x, const float* __restrict__ rw)
{
    int t = blockIdx.x * 8 + (threadIdx.x >> 5);
    int lane = threadIdx.x & 31;
    const float* xr = x + (size_t)t * DIM;
    float p[8];
#pragma unroll
    for (int e = 0; e < 8; e++) p[e] = 0.f;
    for (int k = lane; k < DIM; k += 32) {
        float xv = xr[k];
#pragma unroll
        for (int e = 0; e < 8; e++) p[e] += xv * rw[e * DIM + k];
    }
#pragma unroll
    for (int e = 0; e < 8; e++)
#pragma unroll
        for (int o = 16; o > 0; o >>= 1) p[e] += __shfl_xor_sync(~0u, p[e], o);
    if (lane == 0) {
        float best = p[0]; int bi = 0;
#pragma unroll
        for (int e = 1; e < 8; e++) if (p[e] > best) { best = p[e]; bi = e; }
        float gate = 1.0f / (1.0f + expf(-best));
        int pos = atomicAdd(&g_cnt[bi], 1);
        g_list[bi * NT_TOK + pos] = t;
        g_gate[bi * NT_TOK + pos] = gate;
    }
}

__global__ void finalize_kernel() {
    int o = 0;
    for (int e = 0; e < 8; e++) { g_off[e] = o; o += g_cnt[e]; }
    g_off[8] = NT_TOK;
}

// ---------------- gather: g_X[slot] = tf32(gate * x[tok]) ----------------
__global__ __launch_bounds__(256) void gather_kernel(const float* __restrict__ x)
{
    int row = blockIdx.x;
    int tok; float gate;
    if (row < NT_TOK) {
        int e = 0;
#pragma unroll
        for (int i = 1; i < 8; i++) if (row >= g_off[i]) e = i;
        int idx = row - g_off[e];
        tok  = g_list[e * NT_TOK + idx];
        gate = g_gate[e * NT_TOK + idx];
    } else { tok = row - NT_TOK; gate = 1.f; }
    const float4* src = (const float4*)(x + (size_t)tok * DIM);
    float4* dst = (float4*)(g_X + (size_t)row * DIM);
    for (int j = threadIdx.x; j < DIM / 4; j += 256) {
        float4 v = src[j];
        v.x = to_tf32(v.x * gate); v.y = to_tf32(v.y * gate);
        v.z = to_tf32(v.z * gate); v.w = to_tf32(v.w * gate);
        dst[j] = v;
    }
}

// ================= GEMM1 (cg2 pair tile M=256 x N=512 = gate256|up256) =======
// grid: (2*NT_TOK/256, FDIM/256, 9)  -- m-tile fastest => one wave shares B in L2
// cluster (2,1,1) pairs ranks of the SAME (m0, hb). block 544.
__global__ __launch_bounds__(NTHREADS, 1) __cluster_dims__(2, 1, 1)
void gemm1_tc(const float* __restrict__ wgu, const float* __restrict__ sgu)
{
    const int g   = blockIdx.z;
    const int cnt = (g < NEXP) ? g_cnt[g] : NT_TOK;
    const int m0  = (blockIdx.x >> 1) * 256;
    if (m0 >= cnt) return;                   // uniform across the pair
    const int rank = blockIdx.x & 1;
    const int hb  = blockIdx.y;              // 16 h-blocks of 256 cols
    const float* Bsrc = (g < NEXP) ? (wgu + (size_t)g * DIM * TWOF) : sgu;
    const int rowbase = (g < NEXP) ? g_off[g] : NT_TOK;

#if HAS_TCGEN05
    extern __shared__ char smraw[];
    uint32_t sb = (smem_u32(smraw) + 1023u) & ~1023u;
    // hdr: full[4]@0..24 ; done[4]@32..56 ; TP@64
    const uint32_t TP  = sb + 64;
    const uint32_t BUF = sb + 1024;

    const int tid = threadIdx.x, wid = tid >> 5, lane = tid & 31;

    if (wid == 0) { TC_ALLOC_CG2(TP, 512); TC_RELINQ_CG2(); }
    if (tid == 0) {
#pragma unroll
        for (int s = 0; s < 4; s++) { MBAR_INIT(sb + s * 8, 1024); MBAR_INIT(sb + 32 + s * 8, 1); }
    }
    __syncthreads();
    CLUSTER_SYNC();   // mbar init visible before cross-CTA arrivals / peer smem reads
    uint32_t tb;
    asm volatile("ld.shared.b32 %0, [%1];" : "=r"(tb) : "r"(TP));

    const int T = DIM / 32;

    if (tid < 512) {
        // ---- producers: A = 128 rows (this rank's half), B = 256 cols (rank halves per atom)
        const int ar  = tid >> 3;            // 0..63 (+64 for second chunk)
        const int akc = (tid & 7) * 4;       // k float offset
        const float* abase = g_X + (size_t)(rowbase + m0 + rank * 128) * DIM + akc;
        uint32_t aoff[2];
#pragma unroll
        for (int j = 0; j < 2; j++)
            aoff[j] = SW128((uint32_t)((ar + 64 * j) * 128 + akc * 4));

        const int bn  = wid * 16 + (lane & 15);   // smem B row 0..255
        const int bk0 = (lane >> 4) * 4;
        const int atom = bn >> 7, within = bn & 127;
        const int gcol = (atom == 0)
            ? (hb * 256 + rank * 128 + within)                 // gate cols
            : (FDIM + hb * 256 + rank * 128 + within);         // up cols
        const float* bptr = Bsrc + (size_t)bk0 * TWOF + gcol;
        uint32_t boff[4];
#pragma unroll
        for (int i = 0; i < 4; i++)
            boff[i] = SW128((uint32_t)(bn * 128 + (bk0 + 8 * i) * 4));

        float4 rA[2]; float rB[4][4];
#pragma unroll
        for (int j = 0; j < 2; j++) rA[j] = *(const float4*)(abase + (size_t)(ar + 64 * j) * DIM);
#pragma unroll
        for (int i = 0; i < 4; i++)
#pragma unroll
            for (int d = 0; d < 4; d++) rB[i][d] = bptr[(size_t)(8 * i + d) * TWOF];

        int phD[4] = {0, 0, 0, 0};
        for (int t = 0; t < T; t++) {
            const int s = t & 3;
            const uint32_t Ab = BUF + (uint32_t)s * STAGE_BYTES;
            const uint32_t Bb = Ab + 16384;
            if (t >= 4) { MBAR_WAIT(sb + 32 + s * 8, phD[s]); phD[s] ^= 1; }
#pragma unroll
            for (int j = 0; j < 2; j++)
                STS128(Ab + aoff[j], __float_as_uint(rA[j].x), __float_as_uint(rA[j].y),
                                     __float_as_uint(rA[j].z), __float_as_uint(rA[j].w));
#pragma unroll
            for (int i = 0; i < 4; i++)
                STS128(Bb + boff[i], tf32u(rB[i][0]), tf32u(rB[i][1]),
                                     tf32u(rB[i][2]), tf32u(rB[i][3]));
            FENCE_ASYNC();
            MBAR_ARRIVE_LEADER(sb + s * 8);
            if (t + 1 < T) {
                const float* asrc = abase + (t + 1) * 32;
#pragma unroll
                for (int j = 0; j < 2; j++) rA[j] = *(const float4*)(asrc + (size_t)(ar + 64 * j) * DIM);
                const float* bsrc = bptr + (size_t)(t + 1) * 32 * TWOF;
#pragma unroll
                for (int i = 0; i < 4; i++)
#pragma unroll
                    for (int d = 0; d < 4; d++) rB[i][d] = bsrc[(size_t)(8 * i + d) * TWOF];
            }
        }
        { const int sf = (T - 1) & 3; MBAR_WAIT(sb + 32 + sf * 8, phD[sf]); }
    } else if (rank == 0) {
        // ---- MMA warp: leader only
        if (elect_one()) {
            int phF[4] = {0, 0, 0, 0};
            for (int t = 0; t < T; t++) {
                const int s = t & 3;
                const uint32_t Ab = BUF + (uint32_t)s * STAGE_BYTES;
                const uint32_t Bb = Ab + 16384;
                MBAR_WAIT(sb + s * 8, phF[s]); phF[s] ^= 1;
                uint64_t dA = make_desc_sw128(Ab);
                uint64_t dB = make_desc_sw128(Bb);
#pragma unroll
                for (int c = 0; c < 4; c++) {
                    uint32_t en = (t > 0 || c > 0) ? 1u : 0u;
                    mma_tf32_ss_cg2(tb,       dA + c * 2, dB + c * 2,        IDESC_CG2, en);
                    mma_tf32_ss_cg2(tb + 256, dA + c * 2, dB + 1024 + c * 2, IDESC_CG2, en);
                }
                TC_COMMIT_MC_CG2(sb + 32 + s * 8, 0x3);
            }
        }
    }
    TC_FENCE_AFTER();

    // ---- epilogue: my 128 rows x 512 cols (gate atom0 | up atom1) -> g_H ----
    if (wid < 16) {
        const int rloc = (wid & 3) * 32 + lane;
        const int row  = m0 + rank * 128 + rloc;
        const bool ok  = row < cnt;
        const int cq   = wid >> 2;   // 0..3, 64 gate cols each
        const size_t hbase = (size_t)(rowbase + row) * FDIM + hb * 256 + cq * 64;
#pragma unroll
        for (int c = 0; c < 2; c++) {
            uint32_t gr[32], ur[32];
            uint32_t col = (uint32_t)(cq * 64 + c * 32);
            TC_LD_X32(gr, tb + col);
            TC_LD_X32(ur, tb + 256 + col);
            TC_WAIT_LD();
            if (ok) {
                float h[32];
#pragma unroll
                for (int r = 0; r < 32; r++) {
                    float gv = __uint_as_float(gr[r]), uv = __uint_as_float(ur[r]);
                    h[r] = to_tf32(gv / (1.f + expf(-gv)) * uv);
                }
#pragma unroll
                for (int q = 0; q < 8; q++)
                    *(float4*)&g_H[hbase + c * 32 + q * 4] =
                        make_float4(h[q*4], h[q*4+1], h[q*4+2], h[q*4+3]);
            }
        }
    }
    __syncthreads();
    if (tid == 0) {
#pragma unroll
        for (int s = 0; s < 4; s++) { MBAR_INVAL(sb + s * 8); MBAR_INVAL(sb + 32 + s * 8); }
    }
    __syncthreads();
    if (wid == 0) { TC_DEALLOC_CG2(tb, 512); }
    CLUSTER_SYNC();
#else
    // portable fallback
    for (int idx = threadIdx.x; idx < 128 * 256; idx += NTHREADS) {
        int r = idx >> 8, cc = idx & 255;
        int row = m0 + rank * 128 + r;
        if (row >= cnt) continue;
        const float* arow = g_X + (size_t)(rowbase + row) * DIM;
        int col = hb * 256 + cc;
        float sg = 0.f, su = 0.f;
        for (int k = 0; k < DIM; k++) {
            float a = arow[k];
            sg += a * to_tf32(Bsrc[(size_t)k * TWOF + col]);
            su += a * to_tf32(Bsrc[(size_t)k * TWOF + FDIM + col]);
        }
        g_H[(size_t)(rowbase + row) * FDIM + col] = to_tf32(sg / (1.f + expf(-sg)) * su);
    }
#endif
}

// ================= GEMM2 (cg2 pair tile M=256 x N=512) =================
// grid: (2*NT_TOK/256, DIM/512, nz) -- m-tile fastest. cluster (2,1,1), block 544.
__global__ __launch_bounds__(NTHREADS, 1) __cluster_dims__(2, 1, 1)
void gemm2_tc(const float* __restrict__ wdn, const float* __restrict__ sdn,
              float* __restrict__ out, int gstart, int accumulate)
{
    const int g   = gstart + blockIdx.z;
    const int cnt = (g < NEXP) ? g_cnt[g] : NT_TOK;
    const int m0  = (blockIdx.x >> 1) * 256;
    if (m0 >= cnt) return;
    const int rank = blockIdx.x & 1;
    const int n0  = blockIdx.y * 512;
    const float* Bsrc = (g < NEXP) ? (wdn + (size_t)g * FDIM * DIM) : sdn;
    const int rowbase = (g < NEXP) ? g_off[g] : NT_TOK;

#if HAS_TCGEN05
    extern __shared__ char smraw[];
    uint32_t sb = (smem_u32(smraw) + 1023u) & ~1023u;
    const uint32_t TP  = sb + 64;
    const uint32_t BUF = sb + 1024;

    const int tid = threadIdx.x, wid = tid >> 5, lane = tid & 31;

    if (wid == 0) { TC_ALLOC_CG2(TP, 512); TC_RELINQ_CG2(); }
    if (tid == 0) {
#pragma unroll
        for (int s = 0; s < 4; s++) { MBAR_INIT(sb + s * 8, 1024); MBAR_INIT(sb + 32 + s * 8, 1); }
    }
    __syncthreads();
    CLUSTER_SYNC();
    uint32_t tb;
    asm volatile("ld.shared.b32 %0, [%1];" : "=r"(tb) : "r"(TP));

    const int T = FDIM / 32;

    if (tid < 512) {
        const int ar  = tid >> 3;
        const int akc = (tid & 7) * 4;
        const float* abase = g_H + (size_t)(rowbase + m0 + rank * 128) * FDIM + akc;
        uint32_t aoff[2];
#pragma unroll
        for (int j = 0; j < 2; j++)
            aoff[j] = SW128((uint32_t)((ar + 64 * j) * 128 + akc * 4));

        const int bn  = wid * 16 + (lane & 15);
        const int bk0 = (lane >> 4) * 4;
        const int atom = bn >> 7, within = bn & 127;
        const int gcol = n0 + atom * 256 + rank * 128 + within;
        const float* bptr = Bsrc + (size_t)bk0 * DIM + gcol;
        uint32_t boff[4];
#pragma unroll
        for (int i = 0; i < 4; i++)
            boff[i] = SW128((uint32_t)(bn * 128 + (bk0 + 8 * i) * 4));

        float4 rA[2]; float rB[4][4];
#pragma unroll
        for (int j = 0; j < 2; j++) rA[j] = *(const float4*)(abase + (size_t)(ar + 64 * j) * FDIM);
#pragma unroll
        for (int i = 0; i < 4; i++)
#pragma unroll
            for (int d = 0; d < 4; d++) rB[i][d] = bptr[(size_t)(8 * i + d) * DIM];

        int phD[4] = {0, 0, 0, 0};
        for (int t = 0; t < T; t++) {
            const int s = t & 3;
            const uint32_t Ab = BUF + (uint32_t)s * STAGE_BYTES;
            const uint32_t Bb = Ab + 16384;
            if (t >= 4) { MBAR_WAIT(sb + 32 + s * 8, phD[s]); phD[s] ^= 1; }
#pragma unroll
            for (int j = 0; j < 2; j++)
                STS128(Ab + aoff[j], __float_as_uint(rA[j].x), __float_as_uint(rA[j].y),
                                     __float_as_uint(rA[j].z), __float_as_uint(rA[j].w));
#pragma unroll
            for (int i = 0; i < 4; i++)
                STS128(Bb + boff[i], tf32u(rB[i][0]), tf32u(rB[i][1]),
                                     tf32u(rB[i][2]), tf32u(rB[i][3]));
            FENCE_ASYNC();
            MBAR_ARRIVE_LEADER(sb + s * 8);
            if (t + 1 < T) {
                const float* asrc = abase + (t + 1) * 32;
#pragma unroll
                for (int j = 0; j < 2; j++) rA[j] = *(const float4*)(asrc + (size_t)(ar + 64 * j) * FDIM);
                const float* bsrc = bptr + (size_t)(t + 1) * 32 * DIM;
#pragma unroll
                for (int i = 0; i < 4; i++)
#pragma unroll
                    for (int d = 0; d < 4; d++) rB[i][d] = bsrc[(size_t)(8 * i + d) * DIM];
            }
        }
        { const int sf = (T - 1) & 3; MBAR_WAIT(sb + 32 + sf * 8, phD[sf]); }
    } else if (rank == 0) {
        if (elect_one()) {
            int phF[4] = {0, 0, 0, 0};
            for (int t = 0; t < T; t++) {
                const int s = t & 3;
                const uint32_t Ab = BUF + (uint32_t)s * STAGE_BYTES;
                const uint32_t Bb = Ab + 16384;
                MBAR_WAIT(sb + s * 8, phF[s]); phF[s] ^= 1;
                uint64_t dA = make_desc_sw128(Ab);
                uint64_t dB = make_desc_sw128(Bb);
#pragma unroll
                for (int c = 0; c < 4; c++) {
                    uint32_t en = (t > 0 || c > 0) ? 1u : 0u;
                    mma_tf32_ss_cg2(tb,       dA + c * 2, dB + c * 2,        IDESC_CG2, en);
                    mma_tf32_ss_cg2(tb + 256, dA + c * 2, dB + 1024 + c * 2, IDESC_CG2, en);
                }
                TC_COMMIT_MC_CG2(sb + 32 + s * 8, 0x3);
            }
        }
    }
    TC_FENCE_AFTER();

    // ---- epilogue: my 128 rows x 512 out cols ----
    if (wid < 16) {
        const int rloc = (wid & 3) * 32 + lane;
        const int row  = m0 + rank * 128 + rloc;
        const bool ok  = row < cnt;
        int tok = 0;
        if (ok) tok = (g < NEXP) ? g_list[g * NT_TOK + row] : row;
        const int cq = wid >> 2;   // 0..3, 128 cols each
        const size_t obase = (size_t)tok * DIM + n0 + cq * 128;
#pragma unroll
        for (int c = 0; c < 4; c++) {
            uint32_t dr[32];
            uint32_t col = (uint32_t)(cq * 128 + c * 32);
            TC_LD_X32(dr, tb + col);
            TC_WAIT_LD();
            if (ok) {
                if (accumulate) {
#pragma unroll
                    for (int q = 0; q < 8; q++) {
                        float4 o = *(float4*)&out[obase + c * 32 + q * 4];
                        o.x += __uint_as_float(dr[q*4]);   o.y += __uint_as_float(dr[q*4+1]);
                        o.z += __uint_as_float(dr[q*4+2]); o.w += __uint_as_float(dr[q*4+3]);
                        *(float4*)&out[obase + c * 32 + q * 4] = o;
                    }
                } else {
#pragma unroll
                    for (int q = 0; q < 8; q++)
                        *(float4*)&out[obase + c * 32 + q * 4] =
                            make_float4(__uint_as_float(dr[q*4]),   __uint_as_float(dr[q*4+1]),
                                        __uint_as_float(dr[q*4+2]), __uint_as_float(dr[q*4+3]));
                }
            }
        }
    }
    __syncthreads();
    if (tid == 0) {
#pragma unroll
        for (int s = 0; s < 4; s++) { MBAR_INVAL(sb + s * 8); MBAR_INVAL(sb + 32 + s * 8); }
    }
    __syncthreads();
    if (wid == 0) { TC_DEALLOC_CG2(tb, 512); }
    CLUSTER_SYNC();
#else
    // portable fallback
    for (int idx = threadIdx.x; idx < 128 * 512; idx += NTHREADS) {
        int r = idx >> 9, cc = idx & 511;
        int row = m0 + rank * 128 + r;
        if (row >= cnt) continue;
        const float* arow = g_H + (size_t)(rowbase + row) * FDIM;
        int col = n0 + cc;
        float s = 0.f;
        for (int k = 0; k < FDIM; k++)
            s += arow[k] * to_tf32(Bsrc[(size_t)k * DIM + col]);
        int tok = (g < NEXP) ? g_list[g * NT_TOK + row] : row;
        size_t o = (size_t)tok * DIM + col;
        if (accumulate) out[o] += s; else out[o] = s;
    }
#endif
}

// ---------------- launch ----------------
extern "C" void kernel_launch(void* const* d_in, const int* in_sizes, int n_in,
                              void* d_out, int out_size)
{
    const float* x   = (const float*)d_in[0];
    const float* rw  = (const float*)d_in[1];
    const float* wgu = (const float*)d_in[2];
    const float* wdn = (const float*)d_in[3];
    const float* sgu = (const float*)d_in[4];
    const float* sdn = (const float*)d_in[5];
    float* out = (float*)d_out;

    cudaFuncSetAttribute(gemm1_tc, cudaFuncAttributeMaxDynamicSharedMemorySize, SMEM_BYTES);
    cudaFuncSetAttribute(gemm2_tc, cudaFuncAttributeMaxDynamicSharedMemorySize, SMEM_BYTES);

    zero_kernel<<<1, 32>>>();
    router_kernel<<<NT_TOK / 8, 256>>>(x, rw);
    finalize_kernel<<<1, 1>>>();
    gather_kernel<<<2 * NT_TOK, 256>>>(x);
    // m-tile (x) fastest: one launch wave shares the same weight block via L2
    gemm1_tc<<<dim3(2 * (NT_TOK / 256), FDIM / 256, 9), NTHREADS, SMEM_BYTES>>>(wgu, sgu);
    gemm2_tc<<<dim3(2 * (NT_TOK / 256), DIM / 512, NEXP), NTHREADS, SMEM_BYTES>>>(wdn, sdn, out, 0, 0);
    gemm2_tc<<<dim3(2 * (NT_TOK / 256), DIM / 512, 1), NTHREADS, SMEM_BYTES>>>(wdn, sdn, out, 8, 1);
}